// round 14
// baseline (speedup 1.0000x reference)
#include <cuda_runtime.h>
#include <cuda_bf16.h>
#include <cstdint>
#include <math.h>

#define NI 128
#define BSZ 32
#define NS 4
#define SEQ 2048
#define DIM 256
#define SROWS (NI*BSZ*NS)
#define RPB (NI*NS)

typedef unsigned long long ull;
typedef __nv_bfloat16 bf16;
typedef __nv_bfloat162 bf162;

__device__ bf16 g_kbf[BSZ*SEQ*DIM];
__device__ bf16 g_vbf[BSZ*SEQ*DIM];
__device__ bf16 g_vt[BSZ*SEQ*DIM];
__device__ bf16 g_qbf[SROWS*DIM];
__device__ bf16 g_P[(size_t)BSZ*RPB*SEQ];
__device__ float g_psum[SROWS];
__device__ float g_slots[SROWS*DIM];
__device__ float g_qintent[NI*DIM];
__device__ float g_qn[NI*DIM];
__device__ float g_clsn[BSZ*DIM];
__device__ bf16 g_tokh[BSZ*SEQ*DIM];
__device__ bf16 g_slh[SROWS*DIM];
__device__ bf16 g_sll[SROWS*DIM];
__device__ bf16 g_hh[SROWS*DIM];
__device__ bf16 g_tbh[SROWS*2*DIM];
__device__ bf16 g_WkvTh[2*DIM*DIM];
__device__ float g_bkv[2*DIM];
__device__ bf16 g_WqsTh[DIM*DIM];
__device__ bf16 g_WqsTl[DIM*DIM];
__device__ bf16 g_Wf1Th[2*DIM*DIM];
__device__ bf16 g_Wf2Th[2*DIM*DIM];

__device__ __forceinline__ ull fma2(ull a, ull b, ull c){
    ull d; asm("fma.rn.f32x2 %0, %1, %2, %3;" : "=l"(d) : "l"(a),"l"(b),"l"(c)); return d;
}
__device__ __forceinline__ ull pack2(float x, float y){
    ull d; asm("mov.b64 %0, {%1, %2};" : "=l"(d) : "f"(x),"f"(y)); return d;
}
__device__ __forceinline__ float2 up2(ull v){
    float2 r; asm("mov.b64 {%0, %1}, %2;" : "=f"(r.x),"=f"(r.y) : "l"(v)); return r;
}
__device__ __forceinline__ float wsum(float v){
    #pragma unroll
    for(int o=16;o>0;o>>=1) v += __shfl_xor_sync(0xffffffffu, v, o);
    return v;
}
__device__ __forceinline__ uint32_t smem_u32(const void* p){
    uint32_t a; asm("{ .reg .u64 t; cvta.to.shared.u64 t, %1; cvt.u32.u64 %0, t; }" : "=r"(a) : "l"(p));
    return a;
}
#define SW128(o) ((o) ^ (((o)>>3)&0x70))
__device__ __forceinline__ void ldsm4(uint32_t& r0,uint32_t& r1,uint32_t& r2,uint32_t& r3,uint32_t a){
    asm volatile("ldmatrix.sync.aligned.m8n8.x4.shared.b16 {%0,%1,%2,%3}, [%4];"
        : "=r"(r0),"=r"(r1),"=r"(r2),"=r"(r3) : "r"(a) : "memory");
}
__device__ __forceinline__ void mma16816(float* c,uint32_t a0,uint32_t a1,uint32_t a2,uint32_t a3,uint32_t b0,uint32_t b1){
    asm volatile("mma.sync.aligned.m16n8k16.row.col.f32.bf16.bf16.f32 "
        "{%0,%1,%2,%3},{%4,%5,%6,%7},{%8,%9},{%0,%1,%2,%3};"
        : "+f"(c[0]),"+f"(c[1]),"+f"(c[2]),"+f"(c[3])
        : "r"(a0),"r"(a1),"r"(a2),"r"(a3),"r"(b0),"r"(b1));
}
__device__ __forceinline__ void cpa16(uint32_t d, const void* s){
    asm volatile("cp.async.cg.shared.global [%0], [%1], 16;" :: "r"(d), "l"(s));
}
#define CP_COMMIT() asm volatile("cp.async.commit_group;" ::: "memory")
#define CP_WAIT0()  asm volatile("cp.async.wait_group 0;" ::: "memory")
__device__ __forceinline__ float geluf(float x){
    return 0.5f*x*(1.0f+erff(x*0.70710678118654752f));
}

// ============ bf16 NT GEMM, 1-pass, templated mode, pipelined fragments ============
// MODE: 0 softmax (Pb=exp(acc/16), psum atomics); 1 upd (C=acc/psum+res);
// 4 gelu(acc+bias)->Pb; 5 acc+bias+res->C fp32 + Pb/Pl split; 6 kv dual-dest
template<int MODE>
__global__ void __launch_bounds__(256,2) mma_nt(
    const bf16* __restrict__ A, const bf16* __restrict__ B,
    bf16* __restrict__ Pb, bf16* __restrict__ Pl,
    float* __restrict__ psum, float* __restrict__ C,
    int lda, int ldb, int ldc, int K,
    size_t sA, size_t sB, size_t sC,
    const float* __restrict__ res, const float* __restrict__ bias)
{
    extern __shared__ char sm[];
    const uint32_t su = smem_u32(sm);
    const int t = threadIdx.x, wid = t>>5, lane = t&31, z = blockIdx.z;
    const int m0 = blockIdx.y<<7, n0 = blockIdx.x<<7;
    A += (size_t)z*sA + (size_t)m0*lda;
    B += (size_t)z*sB + (size_t)n0*ldb;
    const int row_ld = t>>3, col_ld = t&7;
    const uint32_t swoff = SW128((uint32_t)(row_ld*128 + col_ld*16));
    const int nsteps = K>>6;
    float acc[2][8][4];
    #pragma unroll
    for(int i=0;i<2;i++)
        #pragma unroll
        for(int j=0;j<8;j++){ acc[i][j][0]=0.f; acc[i][j][1]=0.f; acc[i][j][2]=0.f; acc[i][j][3]=0.f; }
    {
        const bf16* Ag = A + col_ld*8;
        const bf16* Bg = B + col_ld*8;
        #pragma unroll
        for(int j=0;j<4;j++){
            cpa16(su + swoff + j*4096, Ag + (size_t)(row_ld + j*32)*lda);
            cpa16(su + 16384 + swoff + j*4096, Bg + (size_t)(row_ld + j*32)*ldb);
        }
        CP_COMMIT(); CP_WAIT0();
    }
    __syncthreads();
    const int mw = (wid&3)<<5, nw = (wid>>2)<<6;
    const int lrow = lane&15, lkhalf = (lane>>4)*16;
    for(int s=0;s<nsteps;s++){
        const uint32_t bufc = su + (uint32_t)((s&1)*32768);
        if(s+1<nsteps){
            const uint32_t bufn = su + (uint32_t)(((s+1)&1)*32768);
            const bf16* Ag = A + (size_t)(s+1)*64 + col_ld*8;
            const bf16* Bg = B + (size_t)(s+1)*64 + col_ld*8;
            #pragma unroll
            for(int j=0;j<4;j++){
                cpa16(bufn + swoff + j*4096, Ag + (size_t)(row_ld + j*32)*lda);
                cpa16(bufn + 16384 + swoff + j*4096, Bg + (size_t)(row_ld + j*32)*ldb);
            }
            CP_COMMIT();
        }
        // ---- pipelined 16-stage (kk x ng) fragment loop ----
        uint32_t af[2][2][4];   // [buf][mf][4]
        uint32_t bfr[2][4];     // [buf][4]
        {
            const int kb0 = lkhalf;  // kk=0
            #pragma unroll
            for(int mf=0;mf<2;mf++){
                int row = mw + mf*16 + lrow;
                ldsm4(af[0][mf][0],af[0][mf][1],af[0][mf][2],af[0][mf][3],
                      bufc + SW128((uint32_t)(row*128 + kb0)));
            }
            int row = nw + lrow;
            ldsm4(bfr[0][0],bfr[0][1],bfr[0][2],bfr[0][3],
                  bufc + 16384 + SW128((uint32_t)(row*128 + kb0)));
        }
        #pragma unroll
        for(int i=0;i<16;i++){
            const int kk=i>>2, ng=i&3;
            const int ab = kk&1, bb = i&1;
            if(i<15){
                const int ni=i+1, nkk=ni>>2, nng=ni&3;
                const int nkb = nkk*32 + lkhalf;
                if(nkk!=kk){
                    #pragma unroll
                    for(int mf=0;mf<2;mf++){
                        int row = mw + mf*16 + lrow;
                        ldsm4(af[nkk&1][mf][0],af[nkk&1][mf][1],af[nkk&1][mf][2],af[nkk&1][mf][3],
                              bufc + SW128((uint32_t)(row*128 + nkb)));
                    }
                }
                int row = nw + nng*16 + lrow;
                ldsm4(bfr[bb^1][0],bfr[bb^1][1],bfr[bb^1][2],bfr[bb^1][3],
                      bufc + 16384 + SW128((uint32_t)(row*128 + nkb)));
            }
            #pragma unroll
            for(int mf=0;mf<2;mf++){
                mma16816(acc[mf][ng*2+0], af[ab][mf][0],af[ab][mf][1],af[ab][mf][2],af[ab][mf][3],
                         bfr[bb][0], bfr[bb][2]);
                mma16816(acc[mf][ng*2+1], af[ab][mf][0],af[ab][mf][1],af[ab][mf][2],af[ab][mf][3],
                         bfr[bb][1], bfr[bb][3]);
            }
        }
        if(s+1<nsteps) CP_WAIT0();
        __syncthreads();
    }
    const int gr = lane>>2, gc = (lane&3)<<1;
    if(MODE==0){
        Pb += (size_t)z*sC;
        #pragma unroll
        for(int mf=0;mf<2;mf++){
            const int r0 = m0 + mw + mf*16 + gr, r1 = r0 + 8;
            float s0=0.f, s1=0.f;
            #pragma unroll
            for(int ng=0;ng<4;ng++){
                #pragma unroll
                for(int h=0;h<2;h++){
                    const int col = n0 + nw + ng*16 + h*8 + gc;
                    float* cc = acc[mf][ng*2+h];
                    float e00=__expf(cc[0]*0.0625f), e01=__expf(cc[1]*0.0625f);
                    float e10=__expf(cc[2]*0.0625f), e11=__expf(cc[3]*0.0625f);
                    bf162 p0; p0.x=__float2bfloat16(e00); p0.y=__float2bfloat16(e01);
                    bf162 p1; p1.x=__float2bfloat16(e10); p1.y=__float2bfloat16(e11);
                    *(bf162*)&Pb[(size_t)r0*ldc + col] = p0;
                    *(bf162*)&Pb[(size_t)r1*ldc + col] = p1;
                    s0 += e00+e01; s1 += e10+e11;
                }
            }
            s0 += __shfl_xor_sync(0xffffffffu, s0, 1);
            s0 += __shfl_xor_sync(0xffffffffu, s0, 2);
            s1 += __shfl_xor_sync(0xffffffffu, s1, 1);
            s1 += __shfl_xor_sync(0xffffffffu, s1, 2);
            if((lane&3)==0){
                atomicAdd(&psum[z*RPB + r0], s0);
                atomicAdd(&psum[z*RPB + r1], s1);
            }
        }
    } else if(MODE==1){
        C += (size_t)z*sC;
        const float* rz = res + (size_t)z*sC;
        #pragma unroll
        for(int mf=0;mf<2;mf++){
            const int r0 = m0 + mw + mf*16 + gr, r1 = r0 + 8;
            const float i0 = 1.0f/psum[z*RPB + r0];
            const float i1 = 1.0f/psum[z*RPB + r1];
            #pragma unroll
            for(int ng=0;ng<4;ng++){
                #pragma unroll
                for(int h=0;h<2;h++){
                    const int col = n0 + nw + ng*16 + h*8 + gc;
                    float* cc = acc[mf][ng*2+h];
                    C[(size_t)r0*ldc + col]   = cc[0]*i0 + rz[(size_t)r0*ldc + col];
                    C[(size_t)r0*ldc + col+1] = cc[1]*i0 + rz[(size_t)r0*ldc + col+1];
                    C[(size_t)r1*ldc + col]   = cc[2]*i1 + rz[(size_t)r1*ldc + col];
                    C[(size_t)r1*ldc + col+1] = cc[3]*i1 + rz[(size_t)r1*ldc + col+1];
                }
            }
        }
    } else if(MODE==6){
        #pragma unroll
        for(int mf=0;mf<2;mf++){
            const int r0 = m0 + mw + mf*16 + gr, r1 = r0 + 8;
            #pragma unroll
            for(int ng=0;ng<4;ng++){
                #pragma unroll
                for(int h=0;h<2;h++){
                    const int col = n0 + nw + ng*16 + h*8 + gc;
                    float* cc = acc[mf][ng*2+h];
                    float b0=bias[col], b1=bias[col+1];
                    bf162 p0; p0.x=__float2bfloat16(cc[0]+b0); p0.y=__float2bfloat16(cc[1]+b1);
                    bf162 p1; p1.x=__float2bfloat16(cc[2]+b0); p1.y=__float2bfloat16(cc[3]+b1);
                    bf16* dst = (col < 256) ? Pb : Pl;
                    const int c2 = col & 255;
                    *(bf162*)&dst[(size_t)r0*256 + c2] = p0;
                    *(bf162*)&dst[(size_t)r1*256 + c2] = p1;
                }
            }
        }
    } else {
        #pragma unroll
        for(int mf=0;mf<2;mf++){
            const int r0 = m0 + mw + mf*16 + gr, r1 = r0 + 8;
            #pragma unroll
            for(int ng=0;ng<4;ng++){
                #pragma unroll
                for(int h=0;h<2;h++){
                    const int col = n0 + nw + ng*16 + h*8 + gc;
                    float* cc = acc[mf][ng*2+h];
                    float b0=bias[col], b1=bias[col+1];
                    float x00=cc[0]+b0, x01=cc[1]+b1, x10=cc[2]+b0, x11=cc[3]+b1;
                    if(MODE==4){ x00=geluf(x00); x01=geluf(x01); x10=geluf(x10); x11=geluf(x11); }
                    if(MODE==5){
                        x00 += res[(size_t)r0*ldc + col];
                        x01 += res[(size_t)r0*ldc + col + 1];
                        x10 += res[(size_t)r1*ldc + col];
                        x11 += res[(size_t)r1*ldc + col + 1];
                        C[(size_t)r0*ldc + col]   = x00; C[(size_t)r0*ldc + col+1] = x01;
                        C[(size_t)r1*ldc + col]   = x10; C[(size_t)r1*ldc + col+1] = x11;
                    }
                    bf162 p0; p0.x=__float2bfloat16(x00); p0.y=__float2bfloat16(x01);
                    bf162 p1; p1.x=__float2bfloat16(x10); p1.y=__float2bfloat16(x11);
                    *(bf162*)&Pb[(size_t)r0*ldc + col] = p0;
                    *(bf162*)&Pb[(size_t)r1*ldc + col] = p1;
                    if(MODE==5){
                        bf162 q0, q1;
                        q0.x=__float2bfloat16(x00-__bfloat162float(p0.x));
                        q0.y=__float2bfloat16(x01-__bfloat162float(p0.y));
                        q1.x=__float2bfloat16(x10-__bfloat162float(p1.x));
                        q1.y=__float2bfloat16(x11-__bfloat162float(p1.y));
                        *(bf162*)&Pl[(size_t)r0*ldc + col] = q0;
                        *(bf162*)&Pl[(size_t)r1*ldc + col] = q1;
                    }
                }
            }
        }
    }
}

// ============ split-bf16 3-pass NT GEMM (qslot) + psum zeroing ============
__global__ void __launch_bounds__(256,2) mma_nt3(
    const bf16* __restrict__ Ah, const bf16* __restrict__ Al,
    const bf16* __restrict__ Bh, const bf16* __restrict__ Bl,
    const float* __restrict__ bias, const float* __restrict__ ext,
    bf16* __restrict__ Cbh, float* __restrict__ psum,
    int ldc, int K, size_t sA, size_t sC)
{
    extern __shared__ char sm[];
    const uint32_t su = smem_u32(sm);
    const int t = threadIdx.x, wid = t>>5, lane = t&31, z = blockIdx.z;
    const int m0 = blockIdx.y<<7, n0 = blockIdx.x<<7;
    if(blockIdx.x==0 && t<128) psum[z*RPB + m0 + t] = 0.f;
    Ah += (size_t)z*sA + (size_t)m0*K;
    Al += (size_t)z*sA + (size_t)m0*K;
    Bh += (size_t)n0*K;
    Bl += (size_t)n0*K;
    const int row_ld = t>>3, col_ld = t&7;
    const uint32_t swoff = SW128((uint32_t)(row_ld*128 + col_ld*16));
    const int nsteps = K>>6;
    const uint32_t BH = su + 65536, BL = su + 81920;
    float acc[2][8][4];
    #pragma unroll
    for(int i=0;i<2;i++)
        #pragma unroll
        for(int j=0;j<8;j++){ acc[i][j][0]=0.f; acc[i][j][1]=0.f; acc[i][j][2]=0.f; acc[i][j][3]=0.f; }
    {
        #pragma unroll
        for(int j=0;j<4;j++){
            size_t ro = (size_t)(row_ld + j*32)*K + col_ld*8;
            cpa16(su +         swoff + j*4096, Ah + ro);
            cpa16(su + 16384 + swoff + j*4096, Al + ro);
            cpa16(BH + swoff + j*4096, Bh + ro);
            cpa16(BL + swoff + j*4096, Bl + ro);
        }
        CP_COMMIT(); CP_WAIT0();
    }
    __syncthreads();
    const int mw = (wid&3)<<5, nw = (wid>>2)<<6;
    for(int s=0;s<nsteps;s++){
        const uint32_t bufc = su + (uint32_t)((s&1)*32768);
        if(s+1<nsteps){
            const uint32_t bufn = su + (uint32_t)(((s+1)&1)*32768);
            const size_t ko = (size_t)(s+1)*64 + col_ld*8;
            #pragma unroll
            for(int j=0;j<4;j++){
                size_t ro = (size_t)(row_ld + j*32)*K + ko;
                cpa16(bufn +         swoff + j*4096, Ah + ro);
                cpa16(bufn + 16384 + swoff + j*4096, Al + ro);
            }
            CP_COMMIT();
        }
        #pragma unroll
        for(int kk=0;kk<4;kk++){
            const int kb = kk*32 + ((lane>>4)*16);
            uint32_t ah[2][4], al[2][4];
            #pragma unroll
            for(int mf=0;mf<2;mf++){
                int row = mw + mf*16 + (lane&15);
                uint32_t so = SW128((uint32_t)(row*128 + kb));
                ldsm4(ah[mf][0],ah[mf][1],ah[mf][2],ah[mf][3], bufc + so);
                ldsm4(al[mf][0],al[mf][1],al[mf][2],al[mf][3], bufc + 16384 + so);
            }
            #pragma unroll
            for(int ng=0;ng<4;ng++){
                int row = nw + ng*16 + (lane&15);
                uint32_t so = SW128((uint32_t)(row*128 + kb));
                uint32_t bh0,bh1,bh2,bh3, bl0,bl1,bl2,bl3;
                ldsm4(bh0,bh1,bh2,bh3, BH + so);
                ldsm4(bl0,bl1,bl2,bl3, BL + so);
                #pragma unroll
                for(int mf=0;mf<2;mf++){
                    mma16816(acc[mf][ng*2+0], ah[mf][0],ah[mf][1],ah[mf][2],ah[mf][3], bh0, bh2);
                    mma16816(acc[mf][ng*2+1], ah[mf][0],ah[mf][1],ah[mf][2],ah[mf][3], bh1, bh3);
                    mma16816(acc[mf][ng*2+0], ah[mf][0],ah[mf][1],ah[mf][2],ah[mf][3], bl0, bl2);
                    mma16816(acc[mf][ng*2+1], ah[mf][0],ah[mf][1],ah[mf][2],ah[mf][3], bl1, bl3);
                    mma16816(acc[mf][ng*2+0], al[mf][0],al[mf][1],al[mf][2],al[mf][3], bh0, bh2);
                    mma16816(acc[mf][ng*2+1], al[mf][0],al[mf][1],al[mf][2],al[mf][3], bh1, bh3);
                }
            }
        }
        __syncthreads();
        if(s+1<nsteps){
            const size_t ko = (size_t)(s+1)*64 + col_ld*8;
            #pragma unroll
            for(int j=0;j<4;j++){
                size_t ro = (size_t)(row_ld + j*32)*K + ko;
                cpa16(BH + swoff + j*4096, Bh + ro);
                cpa16(BL + swoff + j*4096, Bl + ro);
            }
            CP_COMMIT(); CP_WAIT0();
            __syncthreads();
        }
    }
    Cbh += (size_t)z*sC;
    const int gr = lane>>2, gc = (lane&3)<<1;
    #pragma unroll
    for(int mf=0;mf<2;mf++){
        const int r0 = m0 + mw + mf*16 + gr, r1 = r0 + 8;
        #pragma unroll
        for(int ng=0;ng<4;ng++){
            #pragma unroll
            for(int h=0;h<2;h++){
                const int col = n0 + nw + ng*16 + h*8 + gc;
                float* cc = acc[mf][ng*2+h];
                float b0=bias[col], b1=bias[col+1];
                float x00=cc[0]+b0+ext[(size_t)(r0>>2)*ldc + col];
                float x01=cc[1]+b1+ext[(size_t)(r0>>2)*ldc + col + 1];
                float x10=cc[2]+b0+ext[(size_t)(r1>>2)*ldc + col];
                float x11=cc[3]+b1+ext[(size_t)(r1>>2)*ldc + col + 1];
                bf162 p0; p0.x=__float2bfloat16(x00); p0.y=__float2bfloat16(x01);
                bf162 p1; p1.x=__float2bfloat16(x10); p1.y=__float2bfloat16(x11);
                *(bf162*)&Cbh[(size_t)r0*ldc + col] = p0;
                *(bf162*)&Cbh[(size_t)r1*ldc + col] = p1;
            }
        }
    }
}

__global__ void __launch_bounds__(256) f2bf_kernel(
    const float* __restrict__ x, bf16* __restrict__ y, int n4)
{
    int i = blockIdx.x*blockDim.x + threadIdx.x;
    if (i >= n4) return;
    float4 v = ((const float4*)x)[i];
    bf162 a; a.x=__float2bfloat16(v.x); a.y=__float2bfloat16(v.y);
    bf162 b; b.x=__float2bfloat16(v.z); b.y=__float2bfloat16(v.w);
    ((bf162*)y)[2*i] = a;
    ((bf162*)y)[2*i+1] = b;
}

__global__ void __launch_bounds__(256) prep_weights_kernel(
    const float* __restrict__ Wk, const float* __restrict__ Wv,
    const float* __restrict__ Wqs, const float* __restrict__ Wf1,
    const float* __restrict__ Wf2, const float* __restrict__ bk,
    const float* __restrict__ bv,
    bf16* __restrict__ WkvTh, bf16* __restrict__ WqsTh, bf16* __restrict__ WqsTl,
    bf16* __restrict__ Wf1Th, bf16* __restrict__ Wf2Th, float* __restrict__ bkv)
{
    __shared__ float tl[32][33];
    const int zz = blockIdx.z, t = threadIdx.x, r = t>>5, c = t&31;
    if(zz==0 && blockIdx.x==8 && blockIdx.y==0){
        bkv[t] = bk[t]; bkv[256+t] = bv[t];
        return;
    }
    const float* W; bf16 *Th, *Tl=nullptr; int K, N, noff=0;
    if(zz==0){ W=Wk; Th=WkvTh; K=DIM; N=DIM; }
    else if(zz==1){ W=Wv; Th=WkvTh; K=DIM; N=DIM; noff=256; }
    else if(zz==2){ W=Wqs; Th=WqsTh; Tl=WqsTl; K=DIM; N=DIM; }
    else if(zz==3){ W=Wf1; Th=Wf1Th; K=DIM; N=2*DIM; }
    else { W=Wf2; Th=Wf2Th; K=2*DIM; N=DIM; }
    const int k0 = blockIdx.x<<5, n0 = blockIdx.y<<5;
    if(k0 >= K || n0 >= N) return;
    #pragma unroll
    for(int j=0;j<4;j++)
        tl[r+j*8][c] = W[(size_t)(k0+r+j*8)*N + n0 + c];
    __syncthreads();
    #pragma unroll
    for(int j=0;j<4;j++){
        float x = tl[c][r+j*8];
        bf16 h = __float2bfloat16(x);
        Th[(size_t)(noff+n0+r+j*8)*K + k0 + c] = h;
        if(Tl) Tl[(size_t)(n0+r+j*8)*K + k0 + c] = __float2bfloat16(x-__bfloat162float(h));
    }
}

__global__ void __launch_bounds__(256) transpose_bf_kernel(
    const bf16* __restrict__ v, bf16* __restrict__ vt)
{
    __shared__ bf16 tl[64][65];
    const int s0 = blockIdx.x<<6, d0 = blockIdx.y<<6, z = blockIdx.z;
    const bf16* vz = v + (size_t)z*SEQ*DIM;
    bf16* vtz = vt + (size_t)z*SEQ*DIM;
    const int t = threadIdx.x;
    #pragma unroll
    for(int j=0;j<16;j++){
        int idx = j*256 + t, r = idx>>6, c = idx&63;
        tl[r][c] = vz[(size_t)(s0+r)*DIM + d0 + c];
    }
    __syncthreads();
    #pragma unroll
    for(int j=0;j<16;j++){
        int idx = j*256 + t, r = idx>>6, c = idx&63;
        vtz[(size_t)(d0+r)*SEQ + s0 + c] = tl[c][r];
    }
}

__global__ void __launch_bounds__(256) sgemm_nn(
    const float* __restrict__ A, const float* __restrict__ B,
    const float* __restrict__ bias, float* __restrict__ C,
    int M, int N, int K)
{
    __shared__ float As[8][132];
    __shared__ float Bs[8][128];
    const int t = threadIdx.x;
    const int m0 = blockIdx.y<<7, n0 = blockIdx.x<<7;
    const int arow = t>>1, acol = (t&1)<<2;
    const int brow = t>>5, bcol = (t&31)<<2;
    const float* Ap = A + (size_t)(m0+arow)*K + acol;
    const float* Bp = B + (size_t)brow*N + n0 + bcol;
    float4 ar = *(const float4*)Ap;
    float4 br = *(const float4*)Bp;
    ull c2[8][4];
    #pragma unroll
    for(int i=0;i<8;i++){ c2[i][0]=0; c2[i][1]=0; c2[i][2]=0; c2[i][3]=0; }
    const int tm=(t>>4)<<3, tn=(t&15)<<3;
    const int nt = K>>3;
    for(int kt=0;kt<nt;kt++){
        As[acol+0][arow]=ar.x; As[acol+1][arow]=ar.y;
        As[acol+2][arow]=ar.z; As[acol+3][arow]=ar.w;
        *(float4*)&Bs[brow][bcol]=br;
        __syncthreads();
        if(kt+1<nt){
            ar = *(const float4*)(Ap + ((kt+1)<<3));
            br = *(const float4*)(Bp + (size_t)((kt+1)<<3)*N);
        }
        #pragma unroll
        for(int kk=0;kk<8;kk++){
            float4 a0=*(const float4*)&As[kk][tm];
            float4 a1=*(const float4*)&As[kk][tm+4];
            ulonglong2 w0=*(const ulonglong2*)&Bs[kk][tn];
            ulonglong2 w1=*(const ulonglong2*)&Bs[kk][tn+4];
            float a[8]={a0.x,a0.y,a0.z,a0.w,a1.x,a1.y,a1.z,a1.w};
            #pragma unroll
            for(int i=0;i<8;i++){
                ull ap = pack2(a[i],a[i]);
                c2[i][0]=fma2(ap,w0.x,c2[i][0]);
                c2[i][1]=fma2(ap,w0.y,c2[i][1]);
                c2[i][2]=fma2(ap,w1.x,c2[i][2]);
                c2[i][3]=fma2(ap,w1.y,c2[i][3]);
            }
        }
        __syncthreads();
    }
    #pragma unroll
    for(int i=0;i<8;i++){
        const int row=m0+tm+i;
        float v[8];
        #pragma unroll
        for(int p=0;p<4;p++){ float2 u=up2(c2[i][p]); v[2*p]=u.x; v[2*p+1]=u.y; }
        #pragma unroll
        for(int j=0;j<8;j++) v[j] += bias[n0+tn+j];
        *(float4*)&C[(size_t)row*N + n0+tn]   = make_float4(v[0],v[1],v[2],v[3]);
        *(float4*)&C[(size_t)row*N + n0+tn+4] = make_float4(v[4],v[5],v[6],v[7]);
    }
}

__global__ void init_slots_kernel(const float* __restrict__ noise,
                                  const float* __restrict__ mu,
                                  const float* __restrict__ sigma,
                                  float* __restrict__ slots,
                                  bf16* __restrict__ slh, bf16* __restrict__ sll)
{
    for(int idx = blockIdx.x*blockDim.x + threadIdx.x; idx < SROWS*DIM;
        idx += gridDim.x*blockDim.x){
        int d = idx & 255, ns = (idx>>8)&3, i = (idx>>10)&127, b = idx>>17;
        float val = mu[ns*DIM+d] + noise[(size_t)(((i*BSZ+b)*NS+ns))*DIM+d]*sigma[ns*DIM+d];
        slots[idx] = val;
        bf16 hv = __float2bfloat16(val);
        slh[idx] = hv;
        sll[idx] = __float2bfloat16(val - __bfloat162float(hv));
    }
}

__global__ void norm_rows_kernel(const float* __restrict__ iq,
                                 const float* __restrict__ cls,
                                 float* __restrict__ qn, float* __restrict__ clsn)
{
    const int row = blockIdx.x, lane = threadIdx.x;
    const float* src; float* dst;
    if(row < NI){ src = iq + (size_t)row*DIM; dst = qn + (size_t)row*DIM; }
    else        { src = cls + (size_t)(row-NI)*DIM; dst = clsn + (size_t)(row-NI)*DIM; }
    float4 a0=*(const float4*)(src + (lane<<2));
    float4 a1=*(const float4*)(src + 128 + (lane<<2));
    float ss=a0.x*a0.x+a0.y*a0.y+a0.z*a0.z+a0.w*a0.w
            +a1.x*a1.x+a1.y*a1.y+a1.z*a1.z+a1.w*a1.w;
    ss = wsum(ss);
    float inv = 1.0f/fmaxf(sqrtf(ss), 1e-12f);
    *(float4*)(dst+(lane<<2))     = make_float4(a0.x*inv,a0.y*inv,a0.z*inv,a0.w*inv);
    *(float4*)(dst+128+(lane<<2)) = make_float4(a1.x*inv,a1.y*inv,a1.z*inv,a1.w*inv);
}

__global__ void __launch_bounds__(256) ln_fused_kernel(
    float* __restrict__ slots,
    const float* __restrict__ g1, const float* __restrict__ b1,
    const float* __restrict__ g2, const float* __restrict__ b2,
    bf16* __restrict__ hh)
{
    const int row = (blockIdx.x<<3) + (threadIdx.x>>5);
    const int lane = threadIdx.x & 31;
    float* xp = slots + (size_t)row*DIM;
    float4 a0=*(const float4*)(xp+(lane<<2));
    float4 a1=*(const float4*)(xp+128+(lane<<2));
    float v[8]={a0.x,a0.y,a0.z,a0.w,a1.x,a1.y,a1.z,a1.w};
    float s1=0.f,s2=0.f;
    #pragma unroll
    for(int q=0;q<8;q++){ s1+=v[q]; s2+=v[q]*v[q]; }
    s1=wsum(s1); s2=wsum(s2);
    float mean=s1*(1.0f/256.0f);
    float rstd=rsqrtf(s2*(1.0f/256.0f)-mean*mean + 1e-5f);
    float4 g10=*(const float4*)(g1+(lane<<2)),  g11=*(const float4*)(g1+128+(lane<<2));
    float4 b10=*(const float4*)(b1+(lane<<2)),  b11=*(const float4*)(b1+128+(lane<<2));
    float o[8];
    o[0]=(v[0]-mean)*rstd*g10.x+b10.x; o[1]=(v[1]-mean)*rstd*g10.y+b10.y;
    o[2]=(v[2]-mean)*rstd*g10.z+b10.z; o[3]=(v[3]-mean)*rstd*g10.w+b10.w;
    o[4]=(v[4]-mean)*rstd*g11.x+b11.x; o[5]=(v[5]-mean)*rstd*g11.y+b11.y;
    o[6]=(v[6]-mean)*rstd*g11.z+b11.z; o[7]=(v[7]-mean)*rstd*g11.w+b11.w;
    *(float4*)(xp+(lane<<2))     = make_float4(o[0],o[1],o[2],o[3]);
    *(float4*)(xp+128+(lane<<2)) = make_float4(o[4],o[5],o[6],o[7]);
    float t1=0.f,t2=0.f;
    #pragma unroll
    for(int q=0;q<8;q++){ t1+=o[q]; t2+=o[q]*o[q]; }
    t1=wsum(t1); t2=wsum(t2);
    float mean2=t1*(1.0f/256.0f);
    float rstd2=rsqrtf(t2*(1.0f/256.0f)-mean2*mean2 + 1e-5f);
    float4 g20=*(const float4*)(g2+(lane<<2)),  g21=*(const float4*)(g2+128+(lane<<2));
    float4 b20=*(const float4*)(b2+(lane<<2)),  b21=*(const float4*)(b2+128+(lane<<2));
    bf16 hb[8];
    hb[0]=__float2bfloat16((o[0]-mean2)*rstd2*g20.x+b20.x);
    hb[1]=__float2bfloat16((o[1]-mean2)*rstd2*g20.y+b20.y);
    hb[2]=__float2bfloat16((o[2]-mean2)*rstd2*g20.z+b20.z);
    hb[3]=__float2bfloat16((o[3]-mean2)*rstd2*g20.w+b20.w);
    hb[4]=__float2bfloat16((o[4]-mean2)*rstd2*g21.x+b21.x);
    hb[5]=__float2bfloat16((o[5]-mean2)*rstd2*g21.y+b21.y);
    hb[6]=__float2bfloat16((o[6]-mean2)*rstd2*g21.z+b21.z);
    hb[7]=__float2bfloat16((o[7]-mean2)*rstd2*g21.w+b21.w);
    *(uint2*)(hh + (size_t)row*DIM + (lane<<2))       = *(uint2*)hb;
    *(uint2*)(hh + (size_t)row*DIM + 128 + (lane<<2)) = *(uint2*)(hb+4);
}

__global__ void __launch_bounds__(128) final_kernel(
    const float* __restrict__ slots, const float* __restrict__ qn,
    const float* __restrict__ clsn, const float* __restrict__ alpha,
    const float* __restrict__ temp, float* __restrict__ out)
{
    __shared__ float sh[4];
    const int i = blockIdx.x, b = blockIdx.y;
    const int w = threadIdx.x>>5, lane = threadIdx.x&31;
    const size_t base = ((size_t)(b*NI + i))*NS;
    const float* qp = qn + (size_t)i*DIM;
    const float* sp = slots + (base+w)*DIM;
    float ss=0.f, dq=0.f;
    #pragma unroll
    for(int q=0;q<8;q++){
        float x=sp[lane+(q<<5)], y=qp[lane+(q<<5)];
        ss+=x*x; dq+=x*y;
    }
    ss=wsum(ss); dq=wsum(dq);
    if(lane==0) sh[w] = dq / fmaxf(sqrtf(ss), 1e-12f);
    __syncthreads();
    float m=fmaxf(fmaxf(sh[0],sh[1]),fmaxf(sh[2],sh[3]));
    float e0=expf(sh[0]-m),e1=expf(sh[1]-m),e2=expf(sh[2]-m),e3=expf(sh[3]-m);
    float inv=1.0f/(e0+e1+e2+e3);
    float a4[4]={e0*inv,e1*inv,e2*inv,e3*inv};
    __syncthreads();
    const int d0=threadIdx.x, d1=threadIdx.x+128;
    float s0=0.f, s1=0.f;
    #pragma unroll
    for(int n=0;n<4;n++){
        const float* rp = slots + (base+n)*DIM;
        s0 += a4[n]*rp[d0]; s1 += a4[n]*rp[d1];
    }
    float pp = wsum(s0*s0 + s1*s1);
    if(lane==0) sh[w]=pp;
    __syncthreads();
    float nrm = fmaxf(sqrtf(sh[0]+sh[1]+sh[2]+sh[3]), 1e-12f);
    float al = *alpha;
    const float* cp = clsn + (size_t)b*DIM;
    float f0 = cp[d0] + al*s0/nrm;
    float f1 = cp[d1] + al*s1/nrm;
    float dot = wsum(f0*qp[d0] + f1*qp[d1]);
    __syncthreads();
    if(lane==0) sh[w]=dot;
    __syncthreads();
    if(threadIdx.x==0)
        out[(size_t)b*NI + i] = (sh[0]+sh[1]+sh[2]+sh[3]) / fmaxf(*temp, 1e-4f);
}

#define GSYM(p, s) cudaGetSymbolAddress((void**)&p, s)

extern "C" void kernel_launch(void* const* d_in, const int* in_sizes, int n_in,
                              void* d_out, int out_size)
{
    const float* tokens=(const float*)d_in[0];
    const float* cls   =(const float*)d_in[1];
    const float* iq    =(const float*)d_in[2];
    const float* noise =(const float*)d_in[3];
    const float* Wk=(const float*)d_in[4],  *bk=(const float*)d_in[5];
    const float* Wv=(const float*)d_in[6],  *bv=(const float*)d_in[7];
    const float* Wqs=(const float*)d_in[8], *bqs=(const float*)d_in[9];
    const float* Wqi=(const float*)d_in[10],*bqi=(const float*)d_in[11];
    const float* ln1g=(const float*)d_in[12],*ln1b=(const float*)d_in[13];
    const float* ln2g=(const float*)d_in[14],*ln2b=(const float*)d_in[15];
    const float* Wf1=(const float*)d_in[16],*bf1=(const float*)d_in[17];
    const float* Wf2=(const float*)d_in[18],*bf2=(const float*)d_in[19];
    const float* mu=(const float*)d_in[20], *sg=(const float*)d_in[21];
    const float* alpha=(const float*)d_in[22],*temp=(const float*)d_in[23];
    float* out=(float*)d_out;

    float *psum,*slots,*qi,*qnp,*clsn,*bkv;
    bf16 *kbf,*vbf,*vt,*qbf,*P,*tokh,*slh,*sll,*hh,*tbh;
    bf16 *WkvTh,*WqsTh,*WqsTl,*Wf1Th,*Wf2Th;
    GSYM(psum,g_psum); GSYM(slots,g_slots);
    GSYM(qi,g_qintent); GSYM(qnp,g_qn); GSYM(clsn,g_clsn); GSYM(bkv,g_bkv);
    GSYM(kbf,g_kbf); GSYM(vbf,g_vbf); GSYM(vt,g_vt); GSYM(qbf,g_qbf); GSYM(P,g_P);
    GSYM(tokh,g_tokh); GSYM(slh,g_slh); GSYM(sll,g_sll);
    GSYM(hh,g_hh); GSYM(tbh,g_tbh);
    GSYM(WkvTh,g_WkvTh);
    GSYM(WqsTh,g_WqsTh); GSYM(WqsTl,g_WqsTl);
    GSYM(Wf1Th,g_Wf1Th); GSYM(Wf2Th,g_Wf2Th);

    cudaFuncSetAttribute(mma_nt<0>, cudaFuncAttributeMaxDynamicSharedMemorySize, 65536);
    cudaFuncSetAttribute(mma_nt<1>, cudaFuncAttributeMaxDynamicSharedMemorySize, 65536);
    cudaFuncSetAttribute(mma_nt<4>, cudaFuncAttributeMaxDynamicSharedMemorySize, 65536);
    cudaFuncSetAttribute(mma_nt<5>, cudaFuncAttributeMaxDynamicSharedMemorySize, 65536);
    cudaFuncSetAttribute(mma_nt<6>, cudaFuncAttributeMaxDynamicSharedMemorySize, 65536);
    cudaFuncSetAttribute(mma_nt3,   cudaFuncAttributeMaxDynamicSharedMemorySize, 98304);

    // launch order: #4 = mma_nt<6> kv — shape twin of the logits GEMM
    prep_weights_kernel<<<dim3(17,16,5),256>>>(Wk, Wv, Wqs, Wf1, Wf2, bk, bv,
                                               WkvTh, WqsTh, WqsTl, Wf1Th, Wf2Th, bkv);
    f2bf_kernel<<<(BSZ*SEQ*DIM/4+255)/256,256>>>(tokens, tokh, BSZ*SEQ*DIM/4);
    sgemm_nn<<<dim3(2,1),256>>>(iq, Wqi, bqi, qi, NI, DIM, DIM);
    mma_nt<6><<<dim3(4,512,1),256,65536>>>(tokh, WkvTh, kbf, vbf, nullptr, nullptr,
                                           DIM, DIM, 512, DIM, 0,0,0, nullptr, bkv);
    init_slots_kernel<<<4096,256>>>(noise, mu, sg, slots, slh, sll);
    transpose_bf_kernel<<<dim3(SEQ/64, DIM/64, BSZ),256>>>(vbf, vt);
    norm_rows_kernel<<<NI+BSZ,32>>>(iq, cls, qnp, clsn);

    for(int it=0; it<3; it++){
        mma_nt3<<<dim3(2,4,BSZ),256,98304>>>(slh, sll, WqsTh, WqsTl, bqs, qi,
                                             qbf, psum, DIM, DIM, (size_t)RPB*DIM, (size_t)RPB*DIM);
        mma_nt<0><<<dim3(SEQ/128, RPB/128, BSZ),256,65536>>>(
            qbf, kbf, P, nullptr, psum, nullptr, DIM, DIM, SEQ, DIM,
            (size_t)RPB*DIM, (size_t)SEQ*DIM, (size_t)RPB*SEQ, nullptr, nullptr);
        mma_nt<1><<<dim3(DIM/128, RPB/128, BSZ),256,65536>>>(
            P, vt, nullptr, nullptr, psum, slots, SEQ, SEQ, DIM, SEQ,
            (size_t)RPB*SEQ, (size_t)DIM*SEQ, (size_t)RPB*DIM, slots, nullptr);
        ln_fused_kernel<<<SROWS/8,256>>>(slots, ln1g, ln1b, ln2g, ln2b, hh);
        mma_nt<4><<<dim3(4,128,1),256,65536>>>(hh, Wf1Th, tbh, nullptr, nullptr, nullptr,
                                               DIM, DIM, 2*DIM, DIM, 0,0,0, nullptr, bf1);
        mma_nt<5><<<dim3(2,128,1),256,65536>>>(tbh, Wf2Th, slh, sll, nullptr, slots,
                                               2*DIM, 2*DIM, DIM, 2*DIM, 0,0,0, slots, bf2);
    }
    final_kernel<<<dim3(NI,BSZ),128>>>(slots, qnp, clsn, alpha, temp, out);
}

// round 15
// speedup vs baseline: 1.0100x; 1.0100x over previous
#include <cuda_runtime.h>
#include <cuda_bf16.h>
#include <cstdint>
#include <math.h>

#define NI 128
#define BSZ 32
#define NS 4
#define SEQ 2048
#define DIM 256
#define SROWS (NI*BSZ*NS)
#define RPB (NI*NS)

typedef unsigned long long ull;
typedef __nv_bfloat16 bf16;
typedef __nv_bfloat162 bf162;

__device__ bf16 g_kbf[BSZ*SEQ*DIM];
__device__ bf16 g_vbf[BSZ*SEQ*DIM];
__device__ bf16 g_vt[BSZ*SEQ*DIM];
__device__ bf16 g_qbf[SROWS*DIM];
__device__ bf16 g_P[(size_t)BSZ*RPB*SEQ];
__device__ float g_psum[SROWS];
__device__ float g_slots[SROWS*DIM];
__device__ float g_qintent[NI*DIM];
__device__ float g_qn[NI*DIM];
__device__ float g_clsn[BSZ*DIM];
__device__ bf16 g_tokh[BSZ*SEQ*DIM];
__device__ bf16 g_slh[SROWS*DIM];
__device__ bf16 g_sll[SROWS*DIM];
__device__ bf16 g_hh[SROWS*DIM];
__device__ bf16 g_tbh[SROWS*2*DIM];
__device__ bf16 g_WkvTh[2*DIM*DIM];
__device__ float g_bkv[2*DIM];
__device__ bf16 g_WqsTh[DIM*DIM];
__device__ bf16 g_WqsTl[DIM*DIM];
__device__ bf16 g_Wf1Th[2*DIM*DIM];
__device__ bf16 g_Wf2Th[2*DIM*DIM];

__device__ __forceinline__ ull fma2(ull a, ull b, ull c){
    ull d; asm("fma.rn.f32x2 %0, %1, %2, %3;" : "=l"(d) : "l"(a),"l"(b),"l"(c)); return d;
}
__device__ __forceinline__ ull pack2(float x, float y){
    ull d; asm("mov.b64 %0, {%1, %2};" : "=l"(d) : "f"(x),"f"(y)); return d;
}
__device__ __forceinline__ float2 up2(ull v){
    float2 r; asm("mov.b64 {%0, %1}, %2;" : "=f"(r.x),"=f"(r.y) : "l"(v)); return r;
}
__device__ __forceinline__ float wsum(float v){
    #pragma unroll
    for(int o=16;o>0;o>>=1) v += __shfl_xor_sync(0xffffffffu, v, o);
    return v;
}
__device__ __forceinline__ uint32_t smem_u32(const void* p){
    uint32_t a; asm("{ .reg .u64 t; cvta.to.shared.u64 t, %1; cvt.u32.u64 %0, t; }" : "=r"(a) : "l"(p));
    return a;
}
#define SW128(o) ((o) ^ (((o)>>3)&0x70))
__device__ __forceinline__ void ldsm4(uint32_t& r0,uint32_t& r1,uint32_t& r2,uint32_t& r3,uint32_t a){
    asm volatile("ldmatrix.sync.aligned.m8n8.x4.shared.b16 {%0,%1,%2,%3}, [%4];"
        : "=r"(r0),"=r"(r1),"=r"(r2),"=r"(r3) : "r"(a) : "memory");
}
__device__ __forceinline__ void mma16816(float* c,uint32_t a0,uint32_t a1,uint32_t a2,uint32_t a3,uint32_t b0,uint32_t b1){
    asm volatile("mma.sync.aligned.m16n8k16.row.col.f32.bf16.bf16.f32 "
        "{%0,%1,%2,%3},{%4,%5,%6,%7},{%8,%9},{%0,%1,%2,%3};"
        : "+f"(c[0]),"+f"(c[1]),"+f"(c[2]),"+f"(c[3])
        : "r"(a0),"r"(a1),"r"(a2),"r"(a3),"r"(b0),"r"(b1));
}
__device__ __forceinline__ void cpa16(uint32_t d, const void* s){
    asm volatile("cp.async.cg.shared.global [%0], [%1], 16;" :: "r"(d), "l"(s));
}
#define CP_COMMIT() asm volatile("cp.async.commit_group;" ::: "memory")
#define CP_WAIT0()  asm volatile("cp.async.wait_group 0;" ::: "memory")
__device__ __forceinline__ float geluf(float x){
    return 0.5f*x*(1.0f+erff(x*0.70710678118654752f));
}

// ============ bf16 NT GEMM, 1-pass, templated mode, pipelined fragments ============
// MODE: 0 softmax (Pb=exp(acc/16), psum atomics); 4 gelu(acc+bias)->Pb;
// 5 acc+bias+res->C fp32 + Pb/Pl split; 6 kv dual-dest;
// 7 upd split-K: atomicAdd(C, acc/psum[row]); grid.x = (n-tiles)*(2 k-halves)
template<int MODE>
__global__ void __launch_bounds__(256,2) mma_nt(
    const bf16* __restrict__ A, const bf16* __restrict__ B,
    bf16* __restrict__ Pb, bf16* __restrict__ Pl,
    float* __restrict__ psum, float* __restrict__ C,
    int lda, int ldb, int ldc, int K,
    size_t sA, size_t sB, size_t sC,
    const float* __restrict__ res, const float* __restrict__ bias)
{
    extern __shared__ char sm[];
    const uint32_t su = smem_u32(sm);
    const int t = threadIdx.x, wid = t>>5, lane = t&31, z = blockIdx.z;
    const int m0 = blockIdx.y<<7;
    int n0, kh = 0;
    if(MODE==7){ n0 = (int)(blockIdx.x&1)<<7; kh = blockIdx.x>>1; }
    else n0 = blockIdx.x<<7;
    A += (size_t)z*sA + (size_t)m0*lda + (size_t)kh*K;
    B += (size_t)z*sB + (size_t)n0*ldb + (size_t)kh*K;
    const int row_ld = t>>3, col_ld = t&7;
    const uint32_t swoff = SW128((uint32_t)(row_ld*128 + col_ld*16));
    const int nsteps = K>>6;
    float acc[2][8][4];
    #pragma unroll
    for(int i=0;i<2;i++)
        #pragma unroll
        for(int j=0;j<8;j++){ acc[i][j][0]=0.f; acc[i][j][1]=0.f; acc[i][j][2]=0.f; acc[i][j][3]=0.f; }
    {
        const bf16* Ag = A + col_ld*8;
        const bf16* Bg = B + col_ld*8;
        #pragma unroll
        for(int j=0;j<4;j++){
            cpa16(su + swoff + j*4096, Ag + (size_t)(row_ld + j*32)*lda);
            cpa16(su + 16384 + swoff + j*4096, Bg + (size_t)(row_ld + j*32)*ldb);
        }
        CP_COMMIT(); CP_WAIT0();
    }
    __syncthreads();
    const int mw = (wid&3)<<5, nw = (wid>>2)<<6;
    const int lrow = lane&15, lkhalf = (lane>>4)*16;
    for(int s=0;s<nsteps;s++){
        const uint32_t bufc = su + (uint32_t)((s&1)*32768);
        if(s+1<nsteps){
            const uint32_t bufn = su + (uint32_t)(((s+1)&1)*32768);
            const bf16* Ag = A + (size_t)(s+1)*64 + col_ld*8;
            const bf16* Bg = B + (size_t)(s+1)*64 + col_ld*8;
            #pragma unroll
            for(int j=0;j<4;j++){
                cpa16(bufn + swoff + j*4096, Ag + (size_t)(row_ld + j*32)*lda);
                cpa16(bufn + 16384 + swoff + j*4096, Bg + (size_t)(row_ld + j*32)*ldb);
            }
            CP_COMMIT();
        }
        uint32_t af[2][2][4];
        uint32_t bfr[2][4];
        {
            #pragma unroll
            for(int mf=0;mf<2;mf++){
                int row = mw + mf*16 + lrow;
                ldsm4(af[0][mf][0],af[0][mf][1],af[0][mf][2],af[0][mf][3],
                      bufc + SW128((uint32_t)(row*128 + lkhalf)));
            }
            int row = nw + lrow;
            ldsm4(bfr[0][0],bfr[0][1],bfr[0][2],bfr[0][3],
                  bufc + 16384 + SW128((uint32_t)(row*128 + lkhalf)));
        }
        #pragma unroll
        for(int i=0;i<16;i++){
            const int kk=i>>2, ng=i&3;
            const int ab = kk&1, bb = i&1;
            if(i<15){
                const int ni=i+1, nkk=ni>>2, nng=ni&3;
                const int nkb = nkk*32 + lkhalf;
                if(nkk!=kk){
                    #pragma unroll
                    for(int mf=0;mf<2;mf++){
                        int row = mw + mf*16 + lrow;
                        ldsm4(af[nkk&1][mf][0],af[nkk&1][mf][1],af[nkk&1][mf][2],af[nkk&1][mf][3],
                              bufc + SW128((uint32_t)(row*128 + nkb)));
                    }
                }
                int row = nw + nng*16 + lrow;
                ldsm4(bfr[bb^1][0],bfr[bb^1][1],bfr[bb^1][2],bfr[bb^1][3],
                      bufc + 16384 + SW128((uint32_t)(row*128 + nkb)));
            }
            #pragma unroll
            for(int mf=0;mf<2;mf++){
                mma16816(acc[mf][ng*2+0], af[ab][mf][0],af[ab][mf][1],af[ab][mf][2],af[ab][mf][3],
                         bfr[bb][0], bfr[bb][2]);
                mma16816(acc[mf][ng*2+1], af[ab][mf][0],af[ab][mf][1],af[ab][mf][2],af[ab][mf][3],
                         bfr[bb][1], bfr[bb][3]);
            }
        }
        if(s+1<nsteps) CP_WAIT0();
        __syncthreads();
    }
    const int gr = lane>>2, gc = (lane&3)<<1;
    if(MODE==0){
        Pb += (size_t)z*sC;
        #pragma unroll
        for(int mf=0;mf<2;mf++){
            const int r0 = m0 + mw + mf*16 + gr, r1 = r0 + 8;
            float s0=0.f, s1=0.f;
            #pragma unroll
            for(int ng=0;ng<4;ng++){
                #pragma unroll
                for(int h=0;h<2;h++){
                    const int col = n0 + nw + ng*16 + h*8 + gc;
                    float* cc = acc[mf][ng*2+h];
                    float e00=__expf(cc[0]*0.0625f), e01=__expf(cc[1]*0.0625f);
                    float e10=__expf(cc[2]*0.0625f), e11=__expf(cc[3]*0.0625f);
                    bf162 p0; p0.x=__float2bfloat16(e00); p0.y=__float2bfloat16(e01);
                    bf162 p1; p1.x=__float2bfloat16(e10); p1.y=__float2bfloat16(e11);
                    *(bf162*)&Pb[(size_t)r0*ldc + col] = p0;
                    *(bf162*)&Pb[(size_t)r1*ldc + col] = p1;
                    s0 += e00+e01; s1 += e10+e11;
                }
            }
            s0 += __shfl_xor_sync(0xffffffffu, s0, 1);
            s0 += __shfl_xor_sync(0xffffffffu, s0, 2);
            s1 += __shfl_xor_sync(0xffffffffu, s1, 1);
            s1 += __shfl_xor_sync(0xffffffffu, s1, 2);
            if((lane&3)==0){
                atomicAdd(&psum[z*RPB + r0], s0);
                atomicAdd(&psum[z*RPB + r1], s1);
            }
        }
    } else if(MODE==7){
        C += (size_t)z*sC;
        #pragma unroll
        for(int mf=0;mf<2;mf++){
            const int r0 = m0 + mw + mf*16 + gr, r1 = r0 + 8;
            const float i0 = 1.0f/psum[z*RPB + r0];
            const float i1 = 1.0f/psum[z*RPB + r1];
            #pragma unroll
            for(int ng=0;ng<4;ng++){
                #pragma unroll
                for(int h=0;h<2;h++){
                    const int col = n0 + nw + ng*16 + h*8 + gc;
                    float* cc = acc[mf][ng*2+h];
                    atomicAdd(&C[(size_t)r0*ldc + col],   cc[0]*i0);
                    atomicAdd(&C[(size_t)r0*ldc + col+1], cc[1]*i0);
                    atomicAdd(&C[(size_t)r1*ldc + col],   cc[2]*i1);
                    atomicAdd(&C[(size_t)r1*ldc + col+1], cc[3]*i1);
                }
            }
        }
    } else if(MODE==6){
        #pragma unroll
        for(int mf=0;mf<2;mf++){
            const int r0 = m0 + mw + mf*16 + gr, r1 = r0 + 8;
            #pragma unroll
            for(int ng=0;ng<4;ng++){
                #pragma unroll
                for(int h=0;h<2;h++){
                    const int col = n0 + nw + ng*16 + h*8 + gc;
                    float* cc = acc[mf][ng*2+h];
                    float b0=bias[col], b1=bias[col+1];
                    bf162 p0; p0.x=__float2bfloat16(cc[0]+b0); p0.y=__float2bfloat16(cc[1]+b1);
                    bf162 p1; p1.x=__float2bfloat16(cc[2]+b0); p1.y=__float2bfloat16(cc[3]+b1);
                    bf16* dst = (col < 256) ? Pb : Pl;
                    const int c2 = col & 255;
                    *(bf162*)&dst[(size_t)r0*256 + c2] = p0;
                    *(bf162*)&dst[(size_t)r1*256 + c2] = p1;
                }
            }
        }
    } else {
        #pragma unroll
        for(int mf=0;mf<2;mf++){
            const int r0 = m0 + mw + mf*16 + gr, r1 = r0 + 8;
            #pragma unroll
            for(int ng=0;ng<4;ng++){
                #pragma unroll
                for(int h=0;h<2;h++){
                    const int col = n0 + nw + ng*16 + h*8 + gc;
                    float* cc = acc[mf][ng*2+h];
                    float b0=bias[col], b1=bias[col+1];
                    float x00=cc[0]+b0, x01=cc[1]+b1, x10=cc[2]+b0, x11=cc[3]+b1;
                    if(MODE==4){ x00=geluf(x00); x01=geluf(x01); x10=geluf(x10); x11=geluf(x11); }
                    if(MODE==5){
                        x00 += res[(size_t)r0*ldc + col];
                        x01 += res[(size_t)r0*ldc + col + 1];
                        x10 += res[(size_t)r1*ldc + col];
                        x11 += res[(size_t)r1*ldc + col + 1];
                        C[(size_t)r0*ldc + col]   = x00; C[(size_t)r0*ldc + col+1] = x01;
                        C[(size_t)r1*ldc + col]   = x10; C[(size_t)r1*ldc + col+1] = x11;
                    }
                    bf162 p0; p0.x=__float2bfloat16(x00); p0.y=__float2bfloat16(x01);
                    bf162 p1; p1.x=__float2bfloat16(x10); p1.y=__float2bfloat16(x11);
                    *(bf162*)&Pb[(size_t)r0*ldc + col] = p0;
                    *(bf162*)&Pb[(size_t)r1*ldc + col] = p1;
                    if(MODE==5){
                        bf162 q0, q1;
                        q0.x=__float2bfloat16(x00-__bfloat162float(p0.x));
                        q0.y=__float2bfloat16(x01-__bfloat162float(p0.y));
                        q1.x=__float2bfloat16(x10-__bfloat162float(p1.x));
                        q1.y=__float2bfloat16(x11-__bfloat162float(p1.y));
                        *(bf162*)&Pl[(size_t)r0*ldc + col] = q0;
                        *(bf162*)&Pl[(size_t)r1*ldc + col] = q1;
                    }
                }
            }
        }
    }
}

// ============ split-bf16 3-pass NT GEMM (qslot), R9 proven version ============
__global__ void __launch_bounds__(256) mma_nt3(
    const bf16* __restrict__ Ah, const bf16* __restrict__ Al,
    const bf16* __restrict__ Bh, const bf16* __restrict__ Bl,
    const float* __restrict__ bias, const float* __restrict__ ext,
    bf16* __restrict__ Cbh, float* __restrict__ psum,
    int ldc, int K, size_t sA, size_t sC)
{
    extern __shared__ char sm[];
    const uint32_t su = smem_u32(sm);
    const int t = threadIdx.x, wid = t>>5, lane = t&31, z = blockIdx.z;
    const int m0 = blockIdx.y<<7, n0 = blockIdx.x<<7;
    if(blockIdx.x==0 && t<128) psum[z*RPB + m0 + t] = 0.f;
    Ah += (size_t)z*sA + (size_t)m0*K;
    Al += (size_t)z*sA + (size_t)m0*K;
    Bh += (size_t)n0*K;
    Bl += (size_t)n0*K;
    const int row_ld = t>>3, col_ld = t&7;
    const uint32_t swoff = SW128((uint32_t)(row_ld*128 + col_ld*16));
    const int nsteps = K>>6;
    float acc[2][8][4];
    #pragma unroll
    for(int i=0;i<2;i++)
        #pragma unroll
        for(int j=0;j<8;j++){ acc[i][j][0]=0.f; acc[i][j][1]=0.f; acc[i][j][2]=0.f; acc[i][j][3]=0.f; }
    {
        #pragma unroll
        for(int j=0;j<4;j++){
            size_t ro = (size_t)(row_ld + j*32)*K + col_ld*8;
            cpa16(su +         swoff + j*4096, Ah + ro);
            cpa16(su + 16384 + swoff + j*4096, Al + ro);
            cpa16(su + 32768 + swoff + j*4096, Bh + ro);
            cpa16(su + 49152 + swoff + j*4096, Bl + ro);
        }
        CP_COMMIT(); CP_WAIT0();
    }
    __syncthreads();
    const int mw = (wid&3)<<5, nw = (wid>>2)<<6;
    for(int s=0;s<nsteps;s++){
        const uint32_t bufc = su + (uint32_t)((s&1)*65536);
        if(s+1<nsteps){
            const uint32_t bufn = su + (uint32_t)(((s+1)&1)*65536);
            const size_t ko = (size_t)(s+1)*64 + col_ld*8;
            #pragma unroll
            for(int j=0;j<4;j++){
                size_t ro = (size_t)(row_ld + j*32)*K + ko;
                cpa16(bufn +         swoff + j*4096, Ah + ro);
                cpa16(bufn + 16384 + swoff + j*4096, Al + ro);
                cpa16(bufn + 32768 + swoff + j*4096, Bh + ro);
                cpa16(bufn + 49152 + swoff + j*4096, Bl + ro);
            }
            CP_COMMIT();
        }
        #pragma unroll
        for(int kk=0;kk<4;kk++){
            const int kb = kk*32 + ((lane>>4)*16);
            uint32_t ah[2][4], al[2][4];
            #pragma unroll
            for(int mf=0;mf<2;mf++){
                int row = mw + mf*16 + (lane&15);
                uint32_t so = SW128((uint32_t)(row*128 + kb));
                ldsm4(ah[mf][0],ah[mf][1],ah[mf][2],ah[mf][3], bufc + so);
                ldsm4(al[mf][0],al[mf][1],al[mf][2],al[mf][3], bufc + 16384 + so);
            }
            #pragma unroll
            for(int ng=0;ng<4;ng++){
                int row = nw + ng*16 + (lane&15);
                uint32_t so = SW128((uint32_t)(row*128 + kb));
                uint32_t bh0,bh1,bh2,bh3, bl0,bl1,bl2,bl3;
                ldsm4(bh0,bh1,bh2,bh3, bufc + 32768 + so);
                ldsm4(bl0,bl1,bl2,bl3, bufc + 49152 + so);
                #pragma unroll
                for(int mf=0;mf<2;mf++){
                    mma16816(acc[mf][ng*2+0], ah[mf][0],ah[mf][1],ah[mf][2],ah[mf][3], bh0, bh2);
                    mma16816(acc[mf][ng*2+1], ah[mf][0],ah[mf][1],ah[mf][2],ah[mf][3], bh1, bh3);
                    mma16816(acc[mf][ng*2+0], ah[mf][0],ah[mf][1],ah[mf][2],ah[mf][3], bl0, bl2);
                    mma16816(acc[mf][ng*2+1], ah[mf][0],ah[mf][1],ah[mf][2],ah[mf][3], bl1, bl3);
                    mma16816(acc[mf][ng*2+0], al[mf][0],al[mf][1],al[mf][2],al[mf][3], bh0, bh2);
                    mma16816(acc[mf][ng*2+1], al[mf][0],al[mf][1],al[mf][2],al[mf][3], bh1, bh3);
                }
            }
        }
        if(s+1<nsteps) CP_WAIT0();
        __syncthreads();
    }
    Cbh += (size_t)z*sC;
    const int gr = lane>>2, gc = (lane&3)<<1;
    #pragma unroll
    for(int mf=0;mf<2;mf++){
        const int r0 = m0 + mw + mf*16 + gr, r1 = r0 + 8;
        #pragma unroll
        for(int ng=0;ng<4;ng++){
            #pragma unroll
            for(int h=0;h<2;h++){
                const int col = n0 + nw + ng*16 + h*8 + gc;
                float* cc = acc[mf][ng*2+h];
                float b0=bias[col], b1=bias[col+1];
                float x00=cc[0]+b0+ext[(size_t)(r0>>2)*ldc + col];
                float x01=cc[1]+b1+ext[(size_t)(r0>>2)*ldc + col + 1];
                float x10=cc[2]+b0+ext[(size_t)(r1>>2)*ldc + col];
                float x11=cc[3]+b1+ext[(size_t)(r1>>2)*ldc + col + 1];
                bf162 p0; p0.x=__float2bfloat16(x00); p0.y=__float2bfloat16(x01);
                bf162 p1; p1.x=__float2bfloat16(x10); p1.y=__float2bfloat16(x11);
                *(bf162*)&Cbh[(size_t)r0*ldc + col] = p0;
                *(bf162*)&Cbh[(size_t)r1*ldc + col] = p1;
            }
        }
    }
}

__global__ void __launch_bounds__(256) f2bf_kernel(
    const float* __restrict__ x, bf16* __restrict__ y, int n4)
{
    int i = blockIdx.x*blockDim.x + threadIdx.x;
    if (i >= n4) return;
    float4 v = ((const float4*)x)[i];
    bf162 a; a.x=__float2bfloat16(v.x); a.y=__float2bfloat16(v.y);
    bf162 b; b.x=__float2bfloat16(v.z); b.y=__float2bfloat16(v.w);
    ((bf162*)y)[2*i] = a;
    ((bf162*)y)[2*i+1] = b;
}

__global__ void __launch_bounds__(256) prep_weights_kernel(
    const float* __restrict__ Wk, const float* __restrict__ Wv,
    const float* __restrict__ Wqs, const float* __restrict__ Wf1,
    const float* __restrict__ Wf2, const float* __restrict__ bk,
    const float* __restrict__ bv,
    bf16* __restrict__ WkvTh, bf16* __restrict__ WqsTh, bf16* __restrict__ WqsTl,
    bf16* __restrict__ Wf1Th, bf16* __restrict__ Wf2Th, float* __restrict__ bkv)
{
    __shared__ float tl[32][33];
    const int zz = blockIdx.z, t = threadIdx.x, r = t>>5, c = t&31;
    if(zz==0 && blockIdx.x==8 && blockIdx.y==0){
        bkv[t] = bk[t]; bkv[256+t] = bv[t];
        return;
    }
    const float* W; bf16 *Th, *Tl=nullptr; int K, N, noff=0;
    if(zz==0){ W=Wk; Th=WkvTh; K=DIM; N=DIM; }
    else if(zz==1){ W=Wv; Th=WkvTh; K=DIM; N=DIM; noff=256; }
    else if(zz==2){ W=Wqs; Th=WqsTh; Tl=WqsTl; K=DIM; N=DIM; }
    else if(zz==3){ W=Wf1; Th=Wf1Th; K=DIM; N=2*DIM; }
    else { W=Wf2; Th=Wf2Th; K=2*DIM; N=DIM; }
    const int k0 = blockIdx.x<<5, n0 = blockIdx.y<<5;
    if(k0 >= K || n0 >= N) return;
    #pragma unroll
    for(int j=0;j<4;j++)
        tl[r+j*8][c] = W[(size_t)(k0+r+j*8)*N + n0 + c];
    __syncthreads();
    #pragma unroll
    for(int j=0;j<4;j++){
        float x = tl[c][r+j*8];
        bf16 h = __float2bfloat16(x);
        Th[(size_t)(noff+n0+r+j*8)*K + k0 + c] = h;
        if(Tl) Tl[(size_t)(n0+r+j*8)*K + k0 + c] = __float2bfloat16(x-__bfloat162float(h));
    }
}

__global__ void __launch_bounds__(256) transpose_bf_kernel(
    const bf16* __restrict__ v, bf16* __restrict__ vt)
{
    __shared__ bf16 tl[64][65];
    const int s0 = blockIdx.x<<6, d0 = blockIdx.y<<6, z = blockIdx.z;
    const bf16* vz = v + (size_t)z*SEQ*DIM;
    bf16* vtz = vt + (size_t)z*SEQ*DIM;
    const int t = threadIdx.x;
    #pragma unroll
    for(int j=0;j<16;j++){
        int idx = j*256 + t, r = idx>>6, c = idx&63;
        tl[r][c] = vz[(size_t)(s0+r)*DIM + d0 + c];
    }
    __syncthreads();
    #pragma unroll
    for(int j=0;j<16;j++){
        int idx = j*256 + t, r = idx>>6, c = idx&63;
        vtz[(size_t)(d0+r)*SEQ + s0 + c] = tl[c][r];
    }
}

__global__ void __launch_bounds__(256) sgemm_nn(
    const float* __restrict__ A, const float* __restrict__ B,
    const float* __restrict__ bias, float* __restrict__ C,
    int M, int N, int K)
{
    __shared__ float As[8][132];
    __shared__ float Bs[8][128];
    const int t = threadIdx.x;
    const int m0 = blockIdx.y<<7, n0 = blockIdx.x<<7;
    const int arow = t>>1, acol = (t&1)<<2;
    const int brow = t>>5, bcol = (t&31)<<2;
    const float* Ap = A + (size_t)(m0+arow)*K + acol;
    const float* Bp = B + (size_t)brow*N + n0 + bcol;
    float4 ar = *(const float4*)Ap;
    float4 br = *(const float4*)Bp;
    ull c2[8][4];
    #pragma unroll
    for(int i=0;i<8;i++){ c2[i][0]=0; c2[i][1]=0; c2[i][2]=0; c2[i][3]=0; }
    const int tm=(t>>4)<<3, tn=(t&15)<<3;
    const int nt = K>>3;
    for(int kt=0;kt<nt;kt++){
        As[acol+0][arow]=ar.x; As[acol+1][arow]=ar.y;
        As[acol+2][arow]=ar.z; As[acol+3][arow]=ar.w;
        *(float4*)&Bs[brow][bcol]=br;
        __syncthreads();
        if(kt+1<nt){
            ar = *(const float4*)(Ap + ((kt+1)<<3));
            br = *(const float4*)(Bp + (size_t)((kt+1)<<3)*N);
        }
        #pragma unroll
        for(int kk=0;kk<8;kk++){
            float4 a0=*(const float4*)&As[kk][tm];
            float4 a1=*(const float4*)&As[kk][tm+4];
            ulonglong2 w0=*(const ulonglong2*)&Bs[kk][tn];
            ulonglong2 w1=*(const ulonglong2*)&Bs[kk][tn+4];
            float a[8]={a0.x,a0.y,a0.z,a0.w,a1.x,a1.y,a1.z,a1.w};
            #pragma unroll
            for(int i=0;i<8;i++){
                ull ap = pack2(a[i],a[i]);
                c2[i][0]=fma2(ap,w0.x,c2[i][0]);
                c2[i][1]=fma2(ap,w0.y,c2[i][1]);
                c2[i][2]=fma2(ap,w1.x,c2[i][2]);
                c2[i][3]=fma2(ap,w1.y,c2[i][3]);
            }
        }
        __syncthreads();
    }
    #pragma unroll
    for(int i=0;i<8;i++){
        const int row=m0+tm+i;
        float v[8];
        #pragma unroll
        for(int p=0;p<4;p++){ float2 u=up2(c2[i][p]); v[2*p]=u.x; v[2*p+1]=u.y; }
        #pragma unroll
        for(int j=0;j<8;j++) v[j] += bias[n0+tn+j];
        *(float4*)&C[(size_t)row*N + n0+tn]   = make_float4(v[0],v[1],v[2],v[3]);
        *(float4*)&C[(size_t)row*N + n0+tn+4] = make_float4(v[4],v[5],v[6],v[7]);
    }
}

__global__ void init_slots_kernel(const float* __restrict__ noise,
                                  const float* __restrict__ mu,
                                  const float* __restrict__ sigma,
                                  float* __restrict__ slots,
                                  bf16* __restrict__ slh, bf16* __restrict__ sll)
{
    for(int idx = blockIdx.x*blockDim.x + threadIdx.x; idx < SROWS*DIM;
        idx += gridDim.x*blockDim.x){
        int d = idx & 255, ns = (idx>>8)&3, i = (idx>>10)&127, b = idx>>17;
        float val = mu[ns*DIM+d] + noise[(size_t)(((i*BSZ+b)*NS+ns))*DIM+d]*sigma[ns*DIM+d];
        slots[idx] = val;
        bf16 hv = __float2bfloat16(val);
        slh[idx] = hv;
        sll[idx] = __float2bfloat16(val - __bfloat162float(hv));
    }
}

__global__ void norm_rows_kernel(const float* __restrict__ iq,
                                 const float* __restrict__ cls,
                                 float* __restrict__ qn, float* __restrict__ clsn)
{
    const int row = blockIdx.x, lane = threadIdx.x;
    const float* src; float* dst;
    if(row < NI){ src = iq + (size_t)row*DIM; dst = qn + (size_t)row*DIM; }
    else        { src = cls + (size_t)(row-NI)*DIM; dst = clsn + (size_t)(row-NI)*DIM; }
    float4 a0=*(const float4*)(src + (lane<<2));
    float4 a1=*(const float4*)(src + 128 + (lane<<2));
    float ss=a0.x*a0.x+a0.y*a0.y+a0.z*a0.z+a0.w*a0.w
            +a1.x*a1.x+a1.y*a1.y+a1.z*a1.z+a1.w*a1.w;
    ss = wsum(ss);
    float inv = 1.0f/fmaxf(sqrtf(ss), 1e-12f);
    *(float4*)(dst+(lane<<2))     = make_float4(a0.x*inv,a0.y*inv,a0.z*inv,a0.w*inv);
    *(float4*)(dst+128+(lane<<2)) = make_float4(a1.x*inv,a1.y*inv,a1.z*inv,a1.w*inv);
}

__global__ void __launch_bounds__(256) ln_fused_kernel(
    float* __restrict__ slots,
    const float* __restrict__ g1, const float* __restrict__ b1,
    const float* __restrict__ g2, const float* __restrict__ b2,
    bf16* __restrict__ hh)
{
    const int row = (blockIdx.x<<3) + (threadIdx.x>>5);
    const int lane = threadIdx.x & 31;
    float* xp = slots + (size_t)row*DIM;
    float4 a0=*(const float4*)(xp+(lane<<2));
    float4 a1=*(const float4*)(xp+128+(lane<<2));
    float v[8]={a0.x,a0.y,a0.z,a0.w,a1.x,a1.y,a1.z,a1.w};
    float s1=0.f,s2=0.f;
    #pragma unroll
    for(int q=0;q<8;q++){ s1+=v[q]; s2+=v[q]*v[q]; }
    s1=wsum(s1); s2=wsum(s2);
    float mean=s1*(1.0f/256.0f);
    float rstd=rsqrtf(s2*(1.0f/256.0f)-mean*mean + 1e-5f);
    float4 g10=*(const float4*)(g1+(lane<<2)),  g11=*(const float4*)(g1+128+(lane<<2));
    float4 b10=*(const float4*)(b1+(lane<<2)),  b11=*(const float4*)(b1+128+(lane<<2));
    float o[8];
    o[0]=(v[0]-mean)*rstd*g10.x+b10.x; o[1]=(v[1]-mean)*rstd*g10.y+b10.y;
    o[2]=(v[2]-mean)*rstd*g10.z+b10.z; o[3]=(v[3]-mean)*rstd*g10.w+b10.w;
    o[4]=(v[4]-mean)*rstd*g11.x+b11.x; o[5]=(v[5]-mean)*rstd*g11.y+b11.y;
    o[6]=(v[6]-mean)*rstd*g11.z+b11.z; o[7]=(v[7]-mean)*rstd*g11.w+b11.w;
    *(float4*)(xp+(lane<<2))     = make_float4(o[0],o[1],o[2],o[3]);
    *(float4*)(xp+128+(lane<<2)) = make_float4(o[4],o[5],o[6],o[7]);
    float t1=0.f,t2=0.f;
    #pragma unroll
    for(int q=0;q<8;q++){ t1+=o[q]; t2+=o[q]*o[q]; }
    t1=wsum(t1); t2=wsum(t2);
    float mean2=t1*(1.0f/256.0f);
    float rstd2=rsqrtf(t2*(1.0f/256.0f)-mean2*mean2 + 1e-5f);
    float4 g20=*(const float4*)(g2+(lane<<2)),  g21=*(const float4*)(g2+128+(lane<<2));
    float4 b20=*(const float4*)(b2+(lane<<2)),  b21=*(const float4*)(b2+128+(lane<<2));
    bf16 hb[8];
    hb[0]=__float2bfloat16((o[0]-mean2)*rstd2*g20.x+b20.x);
    hb[1]=__float2bfloat16((o[1]-mean2)*rstd2*g20.y+b20.y);
    hb[2]=__float2bfloat16((o[2]-mean2)*rstd2*g20.z+b20.z);
    hb[3]=__float2bfloat16((o[3]-mean2)*rstd2*g20.w+b20.w);
    hb[4]=__float2bfloat16((o[4]-mean2)*rstd2*g21.x+b21.x);
    hb[5]=__float2bfloat16((o[5]-mean2)*rstd2*g21.y+b21.y);
    hb[6]=__float2bfloat16((o[6]-mean2)*rstd2*g21.z+b21.z);
    hb[7]=__float2bfloat16((o[7]-mean2)*rstd2*g21.w+b21.w);
    *(uint2*)(hh + (size_t)row*DIM + (lane<<2))       = *(uint2*)hb;
    *(uint2*)(hh + (size_t)row*DIM + 128 + (lane<<2)) = *(uint2*)(hb+4);
}

__global__ void __launch_bounds__(128) final_kernel(
    const float* __restrict__ slots, const float* __restrict__ qn,
    const float* __restrict__ clsn, const float* __restrict__ alpha,
    const float* __restrict__ temp, float* __restrict__ out)
{
    __shared__ float sh[4];
    const int i = blockIdx.x, b = blockIdx.y;
    const int w = threadIdx.x>>5, lane = threadIdx.x&31;
    const size_t base = ((size_t)(b*NI + i))*NS;
    const float* qp = qn + (size_t)i*DIM;
    const float* sp = slots + (base+w)*DIM;
    float ss=0.f, dq=0.f;
    #pragma unroll
    for(int q=0;q<8;q++){
        float x=sp[lane+(q<<5)], y=qp[lane+(q<<5)];
        ss+=x*x; dq+=x*y;
    }
    ss=wsum(ss); dq=wsum(dq);
    if(lane==0) sh[w] = dq / fmaxf(sqrtf(ss), 1e-12f);
    __syncthreads();
    float m=fmaxf(fmaxf(sh[0],sh[1]),fmaxf(sh[2],sh[3]));
    float e0=expf(sh[0]-m),e1=expf(sh[1]-m),e2=expf(sh[2]-m),e3=expf(sh[3]-m);
    float inv=1.0f/(e0+e1+e2+e3);
    float a4[4]={e0*inv,e1*inv,e2*inv,e3*inv};
    __syncthreads();
    const int d0=threadIdx.x, d1=threadIdx.x+128;
    float s0=0.f, s1=0.f;
    #pragma unroll
    for(int n=0;n<4;n++){
        const float* rp = slots + (base+n)*DIM;
        s0 += a4[n]*rp[d0]; s1 += a4[n]*rp[d1];
    }
    float pp = wsum(s0*s0 + s1*s1);
    if(lane==0) sh[w]=pp;
    __syncthreads();
    float nrm = fmaxf(sqrtf(sh[0]+sh[1]+sh[2]+sh[3]), 1e-12f);
    float al = *alpha;
    const float* cp = clsn + (size_t)b*DIM;
    float f0 = cp[d0] + al*s0/nrm;
    float f1 = cp[d1] + al*s1/nrm;
    float dot = wsum(f0*qp[d0] + f1*qp[d1]);
    __syncthreads();
    if(lane==0) sh[w]=dot;
    __syncthreads();
    if(threadIdx.x==0)
        out[(size_t)b*NI + i] = (sh[0]+sh[1]+sh[2]+sh[3]) / fmaxf(*temp, 1e-4f);
}

#define GSYM(p, s) cudaGetSymbolAddress((void**)&p, s)

extern "C" void kernel_launch(void* const* d_in, const int* in_sizes, int n_in,
                              void* d_out, int out_size)
{
    const float* tokens=(const float*)d_in[0];
    const float* cls   =(const float*)d_in[1];
    const float* iq    =(const float*)d_in[2];
    const float* noise =(const float*)d_in[3];
    const float* Wk=(const float*)d_in[4],  *bk=(const float*)d_in[5];
    const float* Wv=(const float*)d_in[6],  *bv=(const float*)d_in[7];
    const float* Wqs=(const float*)d_in[8], *bqs=(const float*)d_in[9];
    const float* Wqi=(const float*)d_in[10],*bqi=(const float*)d_in[11];
    const float* ln1g=(const float*)d_in[12],*ln1b=(const float*)d_in[13];
    const float* ln2g=(const float*)d_in[14],*ln2b=(const float*)d_in[15];
    const float* Wf1=(const float*)d_in[16],*bf1=(const float*)d_in[17];
    const float* Wf2=(const float*)d_in[18],*bf2=(const float*)d_in[19];
    const float* mu=(const float*)d_in[20], *sg=(const float*)d_in[21];
    const float* alpha=(const float*)d_in[22],*temp=(const float*)d_in[23];
    float* out=(float*)d_out;

    float *psum,*slots,*qi,*qnp,*clsn,*bkv;
    bf16 *kbf,*vbf,*vt,*qbf,*P,*tokh,*slh,*sll,*hh,*tbh;
    bf16 *WkvTh,*WqsTh,*WqsTl,*Wf1Th,*Wf2Th;
    GSYM(psum,g_psum); GSYM(slots,g_slots);
    GSYM(qi,g_qintent); GSYM(qnp,g_qn); GSYM(clsn,g_clsn); GSYM(bkv,g_bkv);
    GSYM(kbf,g_kbf); GSYM(vbf,g_vbf); GSYM(vt,g_vt); GSYM(qbf,g_qbf); GSYM(P,g_P);
    GSYM(tokh,g_tokh); GSYM(slh,g_slh); GSYM(sll,g_sll);
    GSYM(hh,g_hh); GSYM(tbh,g_tbh);
    GSYM(WkvTh,g_WkvTh);
    GSYM(WqsTh,g_WqsTh); GSYM(WqsTl,g_WqsTl);
    GSYM(Wf1Th,g_Wf1Th); GSYM(Wf2Th,g_Wf2Th);

    cudaFuncSetAttribute(mma_nt<0>, cudaFuncAttributeMaxDynamicSharedMemorySize, 65536);
    cudaFuncSetAttribute(mma_nt<4>, cudaFuncAttributeMaxDynamicSharedMemorySize, 65536);
    cudaFuncSetAttribute(mma_nt<5>, cudaFuncAttributeMaxDynamicSharedMemorySize, 65536);
    cudaFuncSetAttribute(mma_nt<6>, cudaFuncAttributeMaxDynamicSharedMemorySize, 65536);
    cudaFuncSetAttribute(mma_nt<7>, cudaFuncAttributeMaxDynamicSharedMemorySize, 65536);
    cudaFuncSetAttribute(mma_nt3,   cudaFuncAttributeMaxDynamicSharedMemorySize, 131072);

    // R9-proven launch order
    init_slots_kernel<<<4096,256>>>(noise, mu, sg, slots, slh, sll);
    norm_rows_kernel<<<NI+BSZ,32>>>(iq, cls, qnp, clsn);
    sgemm_nn<<<dim3(2,1),256>>>(iq, Wqi, bqi, qi, NI, DIM, DIM);
    f2bf_kernel<<<(BSZ*SEQ*DIM/4+255)/256,256>>>(tokens, tokh, BSZ*SEQ*DIM/4);
    prep_weights_kernel<<<dim3(17,16,5),256>>>(Wk, Wv, Wqs, Wf1, Wf2, bk, bv,
                                               WkvTh, WqsTh, WqsTl, Wf1Th, Wf2Th, bkv);
    mma_nt<6><<<dim3(4,512,1),256,65536>>>(tokh, WkvTh, kbf, vbf, nullptr, nullptr,
                                           DIM, DIM, 512, DIM, 0,0,0, nullptr, bkv);
    transpose_bf_kernel<<<dim3(SEQ/64, DIM/64, BSZ),256>>>(vbf, vt);

    for(int it=0; it<3; it++){
        mma_nt3<<<dim3(2,4,BSZ),256,131072>>>(slh, sll, WqsTh, WqsTl, bqs, qi,
                                              qbf, psum, DIM, DIM, (size_t)RPB*DIM, (size_t)RPB*DIM);
        mma_nt<0><<<dim3(SEQ/128, RPB/128, BSZ),256,65536>>>(
            qbf, kbf, P, nullptr, psum, nullptr, DIM, DIM, SEQ, DIM,
            (size_t)RPB*DIM, (size_t)SEQ*DIM, (size_t)RPB*SEQ, nullptr, nullptr);
        // upd split-K: grid.x = 2 n-tiles * 2 k-halves; slots += acc/psum (atomic)
        mma_nt<7><<<dim3(4, RPB/128, BSZ),256,65536>>>(
            P, vt, nullptr, nullptr, psum, slots, SEQ, SEQ, DIM, SEQ/2,
            (size_t)RPB*SEQ, (size_t)DIM*SEQ, (size_t)RPB*DIM, nullptr, nullptr);
        ln_fused_kernel<<<SROWS/8,256>>>(slots, ln1g, ln1b, ln2g, ln2b, hh);
        mma_nt<4><<<dim3(4,128,1),256,65536>>>(hh, Wf1Th, tbh, nullptr, nullptr, nullptr,
                                               DIM, DIM, 2*DIM, DIM, 0,0,0, nullptr, bf1);
        mma_nt<5><<<dim3(2,128,1),256,65536>>>(tbh, Wf2Th, slh, sll, nullptr, slots,
                                               2*DIM, 2*DIM, DIM, 2*DIM, 0,0,0, slots, bf2);
    }
    final_kernel<<<dim3(NI,BSZ),128>>>(slots, qnp, clsn, alpha, temp, out);
}

// round 16
// speedup vs baseline: 1.0146x; 1.0046x over previous
#include <cuda_runtime.h>
#include <cuda_bf16.h>
#include <cstdint>
#include <math.h>

#define NI 128
#define BSZ 32
#define NS 4
#define SEQ 2048
#define DIM 256
#define SROWS (NI*BSZ*NS)
#define RPB (NI*NS)

typedef unsigned long long ull;
typedef __nv_bfloat16 bf16;
typedef __nv_bfloat162 bf162;

__device__ bf16 g_kbf[BSZ*SEQ*DIM];
__device__ bf16 g_vbf[BSZ*SEQ*DIM];
__device__ bf16 g_vt[BSZ*SEQ*DIM];
__device__ bf16 g_qbf[SROWS*DIM];
__device__ bf16 g_P[(size_t)BSZ*RPB*SEQ];
__device__ float g_psum[SROWS];
__device__ float g_slots[SROWS*DIM];
__device__ float g_qintent[NI*DIM];
__device__ float g_qn[NI*DIM];
__device__ float g_clsn[BSZ*DIM];
__device__ bf16 g_tokh[BSZ*SEQ*DIM];
__device__ bf16 g_slh[SROWS*DIM];
__device__ bf16 g_sll[SROWS*DIM];
__device__ bf16 g_hh[SROWS*DIM];
__device__ bf16 g_tbh[SROWS*2*DIM];
__device__ bf16 g_WkvTh[2*DIM*DIM];
__device__ float g_bkv[2*DIM];
__device__ bf16 g_WqsTh[DIM*DIM];
__device__ bf16 g_WqsTl[DIM*DIM];
__device__ bf16 g_Wf1Th[2*DIM*DIM];
__device__ bf16 g_Wf2Th[2*DIM*DIM];

__device__ __forceinline__ ull fma2(ull a, ull b, ull c){
    ull d; asm("fma.rn.f32x2 %0, %1, %2, %3;" : "=l"(d) : "l"(a),"l"(b),"l"(c)); return d;
}
__device__ __forceinline__ ull pack2(float x, float y){
    ull d; asm("mov.b64 %0, {%1, %2};" : "=l"(d) : "f"(x),"f"(y)); return d;
}
__device__ __forceinline__ float2 up2(ull v){
    float2 r; asm("mov.b64 {%0, %1}, %2;" : "=f"(r.x),"=f"(r.y) : "l"(v)); return r;
}
__device__ __forceinline__ float wsum(float v){
    #pragma unroll
    for(int o=16;o>0;o>>=1) v += __shfl_xor_sync(0xffffffffu, v, o);
    return v;
}
__device__ __forceinline__ uint32_t smem_u32(const void* p){
    uint32_t a; asm("{ .reg .u64 t; cvta.to.shared.u64 t, %1; cvt.u32.u64 %0, t; }" : "=r"(a) : "l"(p));
    return a;
}
#define SW128(o) ((o) ^ (((o)>>3)&0x70))
__device__ __forceinline__ void ldsm4(uint32_t& r0,uint32_t& r1,uint32_t& r2,uint32_t& r3,uint32_t a){
    asm volatile("ldmatrix.sync.aligned.m8n8.x4.shared.b16 {%0,%1,%2,%3}, [%4];"
        : "=r"(r0),"=r"(r1),"=r"(r2),"=r"(r3) : "r"(a) : "memory");
}
__device__ __forceinline__ void mma16816(float* c,uint32_t a0,uint32_t a1,uint32_t a2,uint32_t a3,uint32_t b0,uint32_t b1){
    asm volatile("mma.sync.aligned.m16n8k16.row.col.f32.bf16.bf16.f32 "
        "{%0,%1,%2,%3},{%4,%5,%6,%7},{%8,%9},{%0,%1,%2,%3};"
        : "+f"(c[0]),"+f"(c[1]),"+f"(c[2]),"+f"(c[3])
        : "r"(a0),"r"(a1),"r"(a2),"r"(a3),"r"(b0),"r"(b1));
}
__device__ __forceinline__ void cpa16(uint32_t d, const void* s){
    asm volatile("cp.async.cg.shared.global [%0], [%1], 16;" :: "r"(d), "l"(s));
}
#define CP_COMMIT() asm volatile("cp.async.commit_group;" ::: "memory")
#define CP_WAIT0()  asm volatile("cp.async.wait_group 0;" ::: "memory")
__device__ __forceinline__ float geluf(float x){
    return 0.5f*x*(1.0f+erff(x*0.70710678118654752f));
}

// ============ bf16 NT GEMM, 1-pass, templated mode, pipelined fragments ============
// MODE: 0 softmax (Pb=exp(acc/16), psum atomics); 4 gelu(acc+bias)->Pb;
// 5 acc+bias+res->C fp32 + Pb/Pl split; 6 kv dual-dest;
// 7 upd split-K atomicAdd; 8 acc+bias+res->C fp32 only (final-iter Wf2)
template<int MODE>
__global__ void __launch_bounds__(256,2) mma_nt(
    const bf16* __restrict__ A, const bf16* __restrict__ B,
    bf16* __restrict__ Pb, bf16* __restrict__ Pl,
    float* __restrict__ psum, float* __restrict__ C,
    int lda, int ldb, int ldc, int K,
    size_t sA, size_t sB, size_t sC,
    const float* __restrict__ res, const float* __restrict__ bias)
{
    extern __shared__ char sm[];
    const uint32_t su = smem_u32(sm);
    const int t = threadIdx.x, wid = t>>5, lane = t&31, z = blockIdx.z;
    const int m0 = blockIdx.y<<7;
    int n0, kh = 0;
    if(MODE==7){ n0 = (int)(blockIdx.x&1)<<7; kh = blockIdx.x>>1; }
    else n0 = blockIdx.x<<7;
    A += (size_t)z*sA + (size_t)m0*lda + (size_t)kh*K;
    B += (size_t)z*sB + (size_t)n0*ldb + (size_t)kh*K;
    const int row_ld = t>>3, col_ld = t&7;
    const uint32_t swoff = SW128((uint32_t)(row_ld*128 + col_ld*16));
    const int nsteps = K>>6;
    float acc[2][8][4];
    #pragma unroll
    for(int i=0;i<2;i++)
        #pragma unroll
        for(int j=0;j<8;j++){ acc[i][j][0]=0.f; acc[i][j][1]=0.f; acc[i][j][2]=0.f; acc[i][j][3]=0.f; }
    {
        const bf16* Ag = A + col_ld*8;
        const bf16* Bg = B + col_ld*8;
        #pragma unroll
        for(int j=0;j<4;j++){
            cpa16(su + swoff + j*4096, Ag + (size_t)(row_ld + j*32)*lda);
            cpa16(su + 16384 + swoff + j*4096, Bg + (size_t)(row_ld + j*32)*ldb);
        }
        CP_COMMIT(); CP_WAIT0();
    }
    __syncthreads();
    const int mw = (wid&3)<<5, nw = (wid>>2)<<6;
    const int lrow = lane&15, lkhalf = (lane>>4)*16;
    for(int s=0;s<nsteps;s++){
        const uint32_t bufc = su + (uint32_t)((s&1)*32768);
        if(s+1<nsteps){
            const uint32_t bufn = su + (uint32_t)(((s+1)&1)*32768);
            const bf16* Ag = A + (size_t)(s+1)*64 + col_ld*8;
            const bf16* Bg = B + (size_t)(s+1)*64 + col_ld*8;
            #pragma unroll
            for(int j=0;j<4;j++){
                cpa16(bufn + swoff + j*4096, Ag + (size_t)(row_ld + j*32)*lda);
                cpa16(bufn + 16384 + swoff + j*4096, Bg + (size_t)(row_ld + j*32)*ldb);
            }
            CP_COMMIT();
        }
        uint32_t af[2][2][4];
        uint32_t bfr[2][4];
        {
            #pragma unroll
            for(int mf=0;mf<2;mf++){
                int row = mw + mf*16 + lrow;
                ldsm4(af[0][mf][0],af[0][mf][1],af[0][mf][2],af[0][mf][3],
                      bufc + SW128((uint32_t)(row*128 + lkhalf)));
            }
            int row = nw + lrow;
            ldsm4(bfr[0][0],bfr[0][1],bfr[0][2],bfr[0][3],
                  bufc + 16384 + SW128((uint32_t)(row*128 + lkhalf)));
        }
        #pragma unroll
        for(int i=0;i<16;i++){
            const int kk=i>>2, ng=i&3;
            const int ab = kk&1, bb = i&1;
            if(i<15){
                const int ni=i+1, nkk=ni>>2, nng=ni&3;
                const int nkb = nkk*32 + lkhalf;
                if(nkk!=kk){
                    #pragma unroll
                    for(int mf=0;mf<2;mf++){
                        int row = mw + mf*16 + lrow;
                        ldsm4(af[nkk&1][mf][0],af[nkk&1][mf][1],af[nkk&1][mf][2],af[nkk&1][mf][3],
                              bufc + SW128((uint32_t)(row*128 + nkb)));
                    }
                }
                int row = nw + nng*16 + lrow;
                ldsm4(bfr[bb^1][0],bfr[bb^1][1],bfr[bb^1][2],bfr[bb^1][3],
                      bufc + 16384 + SW128((uint32_t)(row*128 + nkb)));
            }
            #pragma unroll
            for(int mf=0;mf<2;mf++){
                mma16816(acc[mf][ng*2+0], af[ab][mf][0],af[ab][mf][1],af[ab][mf][2],af[ab][mf][3],
                         bfr[bb][0], bfr[bb][2]);
                mma16816(acc[mf][ng*2+1], af[ab][mf][0],af[ab][mf][1],af[ab][mf][2],af[ab][mf][3],
                         bfr[bb][1], bfr[bb][3]);
            }
        }
        if(s+1<nsteps) CP_WAIT0();
        __syncthreads();
    }
    const int gr = lane>>2, gc = (lane&3)<<1;
    if(MODE==0){
        Pb += (size_t)z*sC;
        #pragma unroll
        for(int mf=0;mf<2;mf++){
            const int r0 = m0 + mw + mf*16 + gr, r1 = r0 + 8;
            float s0=0.f, s1=0.f;
            #pragma unroll
            for(int ng=0;ng<4;ng++){
                #pragma unroll
                for(int h=0;h<2;h++){
                    const int col = n0 + nw + ng*16 + h*8 + gc;
                    float* cc = acc[mf][ng*2+h];
                    float e00=__expf(cc[0]*0.0625f), e01=__expf(cc[1]*0.0625f);
                    float e10=__expf(cc[2]*0.0625f), e11=__expf(cc[3]*0.0625f);
                    bf162 p0; p0.x=__float2bfloat16(e00); p0.y=__float2bfloat16(e01);
                    bf162 p1; p1.x=__float2bfloat16(e10); p1.y=__float2bfloat16(e11);
                    *(bf162*)&Pb[(size_t)r0*ldc + col] = p0;
                    *(bf162*)&Pb[(size_t)r1*ldc + col] = p1;
                    s0 += e00+e01; s1 += e10+e11;
                }
            }
            s0 += __shfl_xor_sync(0xffffffffu, s0, 1);
            s0 += __shfl_xor_sync(0xffffffffu, s0, 2);
            s1 += __shfl_xor_sync(0xffffffffu, s1, 1);
            s1 += __shfl_xor_sync(0xffffffffu, s1, 2);
            if((lane&3)==0){
                atomicAdd(&psum[z*RPB + r0], s0);
                atomicAdd(&psum[z*RPB + r1], s1);
            }
        }
    } else if(MODE==7){
        C += (size_t)z*sC;
        #pragma unroll
        for(int mf=0;mf<2;mf++){
            const int r0 = m0 + mw + mf*16 + gr, r1 = r0 + 8;
            const float i0 = 1.0f/psum[z*RPB + r0];
            const float i1 = 1.0f/psum[z*RPB + r1];
            #pragma unroll
            for(int ng=0;ng<4;ng++){
                #pragma unroll
                for(int h=0;h<2;h++){
                    const int col = n0 + nw + ng*16 + h*8 + gc;
                    float* cc = acc[mf][ng*2+h];
                    atomicAdd(&C[(size_t)r0*ldc + col],   cc[0]*i0);
                    atomicAdd(&C[(size_t)r0*ldc + col+1], cc[1]*i0);
                    atomicAdd(&C[(size_t)r1*ldc + col],   cc[2]*i1);
                    atomicAdd(&C[(size_t)r1*ldc + col+1], cc[3]*i1);
                }
            }
        }
    } else if(MODE==6){
        #pragma unroll
        for(int mf=0;mf<2;mf++){
            const int r0 = m0 + mw + mf*16 + gr, r1 = r0 + 8;
            #pragma unroll
            for(int ng=0;ng<4;ng++){
                #pragma unroll
                for(int h=0;h<2;h++){
                    const int col = n0 + nw + ng*16 + h*8 + gc;
                    float* cc = acc[mf][ng*2+h];
                    float b0=bias[col], b1=bias[col+1];
                    bf162 p0; p0.x=__float2bfloat16(cc[0]+b0); p0.y=__float2bfloat16(cc[1]+b1);
                    bf162 p1; p1.x=__float2bfloat16(cc[2]+b0); p1.y=__float2bfloat16(cc[3]+b1);
                    bf16* dst = (col < 256) ? Pb : Pl;
                    const int c2 = col & 255;
                    *(bf162*)&dst[(size_t)r0*256 + c2] = p0;
                    *(bf162*)&dst[(size_t)r1*256 + c2] = p1;
                }
            }
        }
    } else {
        #pragma unroll
        for(int mf=0;mf<2;mf++){
            const int r0 = m0 + mw + mf*16 + gr, r1 = r0 + 8;
            #pragma unroll
            for(int ng=0;ng<4;ng++){
                #pragma unroll
                for(int h=0;h<2;h++){
                    const int col = n0 + nw + ng*16 + h*8 + gc;
                    float* cc = acc[mf][ng*2+h];
                    float b0=bias[col], b1=bias[col+1];
                    float x00=cc[0]+b0, x01=cc[1]+b1, x10=cc[2]+b0, x11=cc[3]+b1;
                    if(MODE==4){ x00=geluf(x00); x01=geluf(x01); x10=geluf(x10); x11=geluf(x11); }
                    if(MODE==5 || MODE==8){
                        x00 += res[(size_t)r0*ldc + col];
                        x01 += res[(size_t)r0*ldc + col + 1];
                        x10 += res[(size_t)r1*ldc + col];
                        x11 += res[(size_t)r1*ldc + col + 1];
                        C[(size_t)r0*ldc + col]   = x00; C[(size_t)r0*ldc + col+1] = x01;
                        C[(size_t)r1*ldc + col]   = x10; C[(size_t)r1*ldc + col+1] = x11;
                    }
                    if(MODE!=8){
                        bf162 p0; p0.x=__float2bfloat16(x00); p0.y=__float2bfloat16(x01);
                        bf162 p1; p1.x=__float2bfloat16(x10); p1.y=__float2bfloat16(x11);
                        *(bf162*)&Pb[(size_t)r0*ldc + col] = p0;
                        *(bf162*)&Pb[(size_t)r1*ldc + col] = p1;
                        if(MODE==5){
                            bf162 q0, q1;
                            q0.x=__float2bfloat16(x00-__bfloat162float(p0.x));
                            q0.y=__float2bfloat16(x01-__bfloat162float(p0.y));
                            q1.x=__float2bfloat16(x10-__bfloat162float(p1.x));
                            q1.y=__float2bfloat16(x11-__bfloat162float(p1.y));
                            *(bf162*)&Pl[(size_t)r0*ldc + col] = q0;
                            *(bf162*)&Pl[(size_t)r1*ldc + col] = q1;
                        }
                    }
                }
            }
        }
    }
}

// ============ split-bf16 3-pass NT GEMM (qslot), R9 proven version ============
__global__ void __launch_bounds__(256) mma_nt3(
    const bf16* __restrict__ Ah, const bf16* __restrict__ Al,
    const bf16* __restrict__ Bh, const bf16* __restrict__ Bl,
    const float* __restrict__ bias, const float* __restrict__ ext,
    bf16* __restrict__ Cbh, float* __restrict__ psum,
    int ldc, int K, size_t sA, size_t sC)
{
    extern __shared__ char sm[];
    const uint32_t su = smem_u32(sm);
    const int t = threadIdx.x, wid = t>>5, lane = t&31, z = blockIdx.z;
    const int m0 = blockIdx.y<<7, n0 = blockIdx.x<<7;
    if(blockIdx.x==0 && t<128) psum[z*RPB + m0 + t] = 0.f;
    Ah += (size_t)z*sA + (size_t)m0*K;
    Al += (size_t)z*sA + (size_t)m0*K;
    Bh += (size_t)n0*K;
    Bl += (size_t)n0*K;
    const int row_ld = t>>3, col_ld = t&7;
    const uint32_t swoff = SW128((uint32_t)(row_ld*128 + col_ld*16));
    const int nsteps = K>>6;
    float acc[2][8][4];
    #pragma unroll
    for(int i=0;i<2;i++)
        #pragma unroll
        for(int j=0;j<8;j++){ acc[i][j][0]=0.f; acc[i][j][1]=0.f; acc[i][j][2]=0.f; acc[i][j][3]=0.f; }
    {
        #pragma unroll
        for(int j=0;j<4;j++){
            size_t ro = (size_t)(row_ld + j*32)*K + col_ld*8;
            cpa16(su +         swoff + j*4096, Ah + ro);
            cpa16(su + 16384 + swoff + j*4096, Al + ro);
            cpa16(su + 32768 + swoff + j*4096, Bh + ro);
            cpa16(su + 49152 + swoff + j*4096, Bl + ro);
        }
        CP_COMMIT(); CP_WAIT0();
    }
    __syncthreads();
    const int mw = (wid&3)<<5, nw = (wid>>2)<<6;
    for(int s=0;s<nsteps;s++){
        const uint32_t bufc = su + (uint32_t)((s&1)*65536);
        if(s+1<nsteps){
            const uint32_t bufn = su + (uint32_t)(((s+1)&1)*65536);
            const size_t ko = (size_t)(s+1)*64 + col_ld*8;
            #pragma unroll
            for(int j=0;j<4;j++){
                size_t ro = (size_t)(row_ld + j*32)*K + ko;
                cpa16(bufn +         swoff + j*4096, Ah + ro);
                cpa16(bufn + 16384 + swoff + j*4096, Al + ro);
                cpa16(bufn + 32768 + swoff + j*4096, Bh + ro);
                cpa16(bufn + 49152 + swoff + j*4096, Bl + ro);
            }
            CP_COMMIT();
        }
        #pragma unroll
        for(int kk=0;kk<4;kk++){
            const int kb = kk*32 + ((lane>>4)*16);
            uint32_t ah[2][4], al[2][4];
            #pragma unroll
            for(int mf=0;mf<2;mf++){
                int row = mw + mf*16 + (lane&15);
                uint32_t so = SW128((uint32_t)(row*128 + kb));
                ldsm4(ah[mf][0],ah[mf][1],ah[mf][2],ah[mf][3], bufc + so);
                ldsm4(al[mf][0],al[mf][1],al[mf][2],al[mf][3], bufc + 16384 + so);
            }
            #pragma unroll
            for(int ng=0;ng<4;ng++){
                int row = nw + ng*16 + (lane&15);
                uint32_t so = SW128((uint32_t)(row*128 + kb));
                uint32_t bh0,bh1,bh2,bh3, bl0,bl1,bl2,bl3;
                ldsm4(bh0,bh1,bh2,bh3, bufc + 32768 + so);
                ldsm4(bl0,bl1,bl2,bl3, bufc + 49152 + so);
                #pragma unroll
                for(int mf=0;mf<2;mf++){
                    mma16816(acc[mf][ng*2+0], ah[mf][0],ah[mf][1],ah[mf][2],ah[mf][3], bh0, bh2);
                    mma16816(acc[mf][ng*2+1], ah[mf][0],ah[mf][1],ah[mf][2],ah[mf][3], bh1, bh3);
                    mma16816(acc[mf][ng*2+0], ah[mf][0],ah[mf][1],ah[mf][2],ah[mf][3], bl0, bl2);
                    mma16816(acc[mf][ng*2+1], ah[mf][0],ah[mf][1],ah[mf][2],ah[mf][3], bl1, bl3);
                    mma16816(acc[mf][ng*2+0], al[mf][0],al[mf][1],al[mf][2],al[mf][3], bh0, bh2);
                    mma16816(acc[mf][ng*2+1], al[mf][0],al[mf][1],al[mf][2],al[mf][3], bh1, bh3);
                }
            }
        }
        if(s+1<nsteps) CP_WAIT0();
        __syncthreads();
    }
    Cbh += (size_t)z*sC;
    const int gr = lane>>2, gc = (lane&3)<<1;
    #pragma unroll
    for(int mf=0;mf<2;mf++){
        const int r0 = m0 + mw + mf*16 + gr, r1 = r0 + 8;
        #pragma unroll
        for(int ng=0;ng<4;ng++){
            #pragma unroll
            for(int h=0;h<2;h++){
                const int col = n0 + nw + ng*16 + h*8 + gc;
                float* cc = acc[mf][ng*2+h];
                float b0=bias[col], b1=bias[col+1];
                float x00=cc[0]+b0+ext[(size_t)(r0>>2)*ldc + col];
                float x01=cc[1]+b1+ext[(size_t)(r0>>2)*ldc + col + 1];
                float x10=cc[2]+b0+ext[(size_t)(r1>>2)*ldc + col];
                float x11=cc[3]+b1+ext[(size_t)(r1>>2)*ldc + col + 1];
                bf162 p0; p0.x=__float2bfloat16(x00); p0.y=__float2bfloat16(x01);
                bf162 p1; p1.x=__float2bfloat16(x10); p1.y=__float2bfloat16(x11);
                *(bf162*)&Cbh[(size_t)r0*ldc + col] = p0;
                *(bf162*)&Cbh[(size_t)r1*ldc + col] = p1;
            }
        }
    }
}

__global__ void __launch_bounds__(256) f2bf_kernel(
    const float* __restrict__ x, bf16* __restrict__ y, int n4)
{
    int i = blockIdx.x*blockDim.x + threadIdx.x;
    if (i >= n4) return;
    float4 v = ((const float4*)x)[i];
    bf162 a; a.x=__float2bfloat16(v.x); a.y=__float2bfloat16(v.y);
    bf162 b; b.x=__float2bfloat16(v.z); b.y=__float2bfloat16(v.w);
    ((bf162*)y)[2*i] = a;
    ((bf162*)y)[2*i+1] = b;
}

__global__ void __launch_bounds__(256) prep_weights_kernel(
    const float* __restrict__ Wk, const float* __restrict__ Wv,
    const float* __restrict__ Wqs, const float* __restrict__ Wf1,
    const float* __restrict__ Wf2, const float* __restrict__ bk,
    const float* __restrict__ bv,
    bf16* __restrict__ WkvTh, bf16* __restrict__ WqsTh, bf16* __restrict__ WqsTl,
    bf16* __restrict__ Wf1Th, bf16* __restrict__ Wf2Th, float* __restrict__ bkv)
{
    __shared__ float tl[32][33];
    const int zz = blockIdx.z, t = threadIdx.x, r = t>>5, c = t&31;
    if(zz==0 && blockIdx.x==8 && blockIdx.y==0){
        bkv[t] = bk[t]; bkv[256+t] = bv[t];
        return;
    }
    const float* W; bf16 *Th, *Tl=nullptr; int K, N, noff=0;
    if(zz==0){ W=Wk; Th=WkvTh; K=DIM; N=DIM; }
    else if(zz==1){ W=Wv; Th=WkvTh; K=DIM; N=DIM; noff=256; }
    else if(zz==2){ W=Wqs; Th=WqsTh; Tl=WqsTl; K=DIM; N=DIM; }
    else if(zz==3){ W=Wf1; Th=Wf1Th; K=DIM; N=2*DIM; }
    else { W=Wf2; Th=Wf2Th; K=2*DIM; N=DIM; }
    const int k0 = blockIdx.x<<5, n0 = blockIdx.y<<5;
    if(k0 >= K || n0 >= N) return;
    #pragma unroll
    for(int j=0;j<4;j++)
        tl[r+j*8][c] = W[(size_t)(k0+r+j*8)*N + n0 + c];
    __syncthreads();
    #pragma unroll
    for(int j=0;j<4;j++){
        float x = tl[c][r+j*8];
        bf16 h = __float2bfloat16(x);
        Th[(size_t)(noff+n0+r+j*8)*K + k0 + c] = h;
        if(Tl) Tl[(size_t)(n0+r+j*8)*K + k0 + c] = __float2bfloat16(x-__bfloat162float(h));
    }
}

__global__ void __launch_bounds__(256) transpose_bf_kernel(
    const bf16* __restrict__ v, bf16* __restrict__ vt)
{
    __shared__ bf16 tl[64][65];
    const int s0 = blockIdx.x<<6, d0 = blockIdx.y<<6, z = blockIdx.z;
    const bf16* vz = v + (size_t)z*SEQ*DIM;
    bf16* vtz = vt + (size_t)z*SEQ*DIM;
    const int t = threadIdx.x;
    #pragma unroll
    for(int j=0;j<16;j++){
        int idx = j*256 + t, r = idx>>6, c = idx&63;
        tl[r][c] = vz[(size_t)(s0+r)*DIM + d0 + c];
    }
    __syncthreads();
    #pragma unroll
    for(int j=0;j<16;j++){
        int idx = j*256 + t, r = idx>>6, c = idx&63;
        vtz[(size_t)(d0+r)*SEQ + s0 + c] = tl[c][r];
    }
}

__global__ void __launch_bounds__(256) sgemm_nn(
    const float* __restrict__ A, const float* __restrict__ B,
    const float* __restrict__ bias, float* __restrict__ C,
    int M, int N, int K)
{
    __shared__ float As[8][132];
    __shared__ float Bs[8][128];
    const int t = threadIdx.x;
    const int m0 = blockIdx.y<<7, n0 = blockIdx.x<<7;
    const int arow = t>>1, acol = (t&1)<<2;
    const int brow = t>>5, bcol = (t&31)<<2;
    const float* Ap = A + (size_t)(m0+arow)*K + acol;
    const float* Bp = B + (size_t)brow*N + n0 + bcol;
    float4 ar = *(const float4*)Ap;
    float4 br = *(const float4*)Bp;
    ull c2[8][4];
    #pragma unroll
    for(int i=0;i<8;i++){ c2[i][0]=0; c2[i][1]=0; c2[i][2]=0; c2[i][3]=0; }
    const int tm=(t>>4)<<3, tn=(t&15)<<3;
    const int nt = K>>3;
    for(int kt=0;kt<nt;kt++){
        As[acol+0][arow]=ar.x; As[acol+1][arow]=ar.y;
        As[acol+2][arow]=ar.z; As[acol+3][arow]=ar.w;
        *(float4*)&Bs[brow][bcol]=br;
        __syncthreads();
        if(kt+1<nt){
            ar = *(const float4*)(Ap + ((kt+1)<<3));
            br = *(const float4*)(Bp + (size_t)((kt+1)<<3)*N);
        }
        #pragma unroll
        for(int kk=0;kk<8;kk++){
            float4 a0=*(const float4*)&As[kk][tm];
            float4 a1=*(const float4*)&As[kk][tm+4];
            ulonglong2 w0=*(const ulonglong2*)&Bs[kk][tn];
            ulonglong2 w1=*(const ulonglong2*)&Bs[kk][tn+4];
            float a[8]={a0.x,a0.y,a0.z,a0.w,a1.x,a1.y,a1.z,a1.w};
            #pragma unroll
            for(int i=0;i<8;i++){
                ull ap = pack2(a[i],a[i]);
                c2[i][0]=fma2(ap,w0.x,c2[i][0]);
                c2[i][1]=fma2(ap,w0.y,c2[i][1]);
                c2[i][2]=fma2(ap,w1.x,c2[i][2]);
                c2[i][3]=fma2(ap,w1.y,c2[i][3]);
            }
        }
        __syncthreads();
    }
    #pragma unroll
    for(int i=0;i<8;i++){
        const int row=m0+tm+i;
        float v[8];
        #pragma unroll
        for(int p=0;p<4;p++){ float2 u=up2(c2[i][p]); v[2*p]=u.x; v[2*p+1]=u.y; }
        #pragma unroll
        for(int j=0;j<8;j++) v[j] += bias[n0+tn+j];
        *(float4*)&C[(size_t)row*N + n0+tn]   = make_float4(v[0],v[1],v[2],v[3]);
        *(float4*)&C[(size_t)row*N + n0+tn+4] = make_float4(v[4],v[5],v[6],v[7]);
    }
}

__global__ void init_slots_kernel(const float* __restrict__ noise,
                                  const float* __restrict__ mu,
                                  const float* __restrict__ sigma,
                                  float* __restrict__ slots,
                                  bf16* __restrict__ slh, bf16* __restrict__ sll)
{
    for(int idx = blockIdx.x*blockDim.x + threadIdx.x; idx < SROWS*DIM;
        idx += gridDim.x*blockDim.x){
        int d = idx & 255, ns = (idx>>8)&3, i = (idx>>10)&127, b = idx>>17;
        float val = mu[ns*DIM+d] + noise[(size_t)(((i*BSZ+b)*NS+ns))*DIM+d]*sigma[ns*DIM+d];
        slots[idx] = val;
        bf16 hv = __float2bfloat16(val);
        slh[idx] = hv;
        sll[idx] = __float2bfloat16(val - __bfloat162float(hv));
    }
}

__global__ void norm_rows_kernel(const float* __restrict__ iq,
                                 const float* __restrict__ cls,
                                 float* __restrict__ qn, float* __restrict__ clsn)
{
    const int row = blockIdx.x, lane = threadIdx.x;
    const float* src; float* dst;
    if(row < NI){ src = iq + (size_t)row*DIM; dst = qn + (size_t)row*DIM; }
    else        { src = cls + (size_t)(row-NI)*DIM; dst = clsn + (size_t)(row-NI)*DIM; }
    float4 a0=*(const float4*)(src + (lane<<2));
    float4 a1=*(const float4*)(src + 128 + (lane<<2));
    float ss=a0.x*a0.x+a0.y*a0.y+a0.z*a0.z+a0.w*a0.w
            +a1.x*a1.x+a1.y*a1.y+a1.z*a1.z+a1.w*a1.w;
    ss = wsum(ss);
    float inv = 1.0f/fmaxf(sqrtf(ss), 1e-12f);
    *(float4*)(dst+(lane<<2))     = make_float4(a0.x*inv,a0.y*inv,a0.z*inv,a0.w*inv);
    *(float4*)(dst+128+(lane<<2)) = make_float4(a1.x*inv,a1.y*inv,a1.z*inv,a1.w*inv);
}

__global__ void __launch_bounds__(256) ln_fused_kernel(
    float* __restrict__ slots,
    const float* __restrict__ g1, const float* __restrict__ b1,
    const float* __restrict__ g2, const float* __restrict__ b2,
    bf16* __restrict__ hh)
{
    const int row = (blockIdx.x<<3) + (threadIdx.x>>5);
    const int lane = threadIdx.x & 31;
    float* xp = slots + (size_t)row*DIM;
    float4 a0=*(const float4*)(xp+(lane<<2));
    float4 a1=*(const float4*)(xp+128+(lane<<2));
    float v[8]={a0.x,a0.y,a0.z,a0.w,a1.x,a1.y,a1.z,a1.w};
    float s1=0.f,s2=0.f;
    #pragma unroll
    for(int q=0;q<8;q++){ s1+=v[q]; s2+=v[q]*v[q]; }
    s1=wsum(s1); s2=wsum(s2);
    float mean=s1*(1.0f/256.0f);
    float rstd=rsqrtf(s2*(1.0f/256.0f)-mean*mean + 1e-5f);
    float4 g10=*(const float4*)(g1+(lane<<2)),  g11=*(const float4*)(g1+128+(lane<<2));
    float4 b10=*(const float4*)(b1+(lane<<2)),  b11=*(const float4*)(b1+128+(lane<<2));
    float o[8];
    o[0]=(v[0]-mean)*rstd*g10.x+b10.x; o[1]=(v[1]-mean)*rstd*g10.y+b10.y;
    o[2]=(v[2]-mean)*rstd*g10.z+b10.z; o[3]=(v[3]-mean)*rstd*g10.w+b10.w;
    o[4]=(v[4]-mean)*rstd*g11.x+b11.x; o[5]=(v[5]-mean)*rstd*g11.y+b11.y;
    o[6]=(v[6]-mean)*rstd*g11.z+b11.z; o[7]=(v[7]-mean)*rstd*g11.w+b11.w;
    *(float4*)(xp+(lane<<2))     = make_float4(o[0],o[1],o[2],o[3]);
    *(float4*)(xp+128+(lane<<2)) = make_float4(o[4],o[5],o[6],o[7]);
    float t1=0.f,t2=0.f;
    #pragma unroll
    for(int q=0;q<8;q++){ t1+=o[q]; t2+=o[q]*o[q]; }
    t1=wsum(t1); t2=wsum(t2);
    float mean2=t1*(1.0f/256.0f);
    float rstd2=rsqrtf(t2*(1.0f/256.0f)-mean2*mean2 + 1e-5f);
    float4 g20=*(const float4*)(g2+(lane<<2)),  g21=*(const float4*)(g2+128+(lane<<2));
    float4 b20=*(const float4*)(b2+(lane<<2)),  b21=*(const float4*)(b2+128+(lane<<2));
    bf16 hb[8];
    hb[0]=__float2bfloat16((o[0]-mean2)*rstd2*g20.x+b20.x);
    hb[1]=__float2bfloat16((o[1]-mean2)*rstd2*g20.y+b20.y);
    hb[2]=__float2bfloat16((o[2]-mean2)*rstd2*g20.z+b20.z);
    hb[3]=__float2bfloat16((o[3]-mean2)*rstd2*g20.w+b20.w);
    hb[4]=__float2bfloat16((o[4]-mean2)*rstd2*g21.x+b21.x);
    hb[5]=__float2bfloat16((o[5]-mean2)*rstd2*g21.y+b21.y);
    hb[6]=__float2bfloat16((o[6]-mean2)*rstd2*g21.z+b21.z);
    hb[7]=__float2bfloat16((o[7]-mean2)*rstd2*g21.w+b21.w);
    *(uint2*)(hh + (size_t)row*DIM + (lane<<2))       = *(uint2*)hb;
    *(uint2*)(hh + (size_t)row*DIM + 128 + (lane<<2)) = *(uint2*)(hb+4);
}

__global__ void __launch_bounds__(128) final_kernel(
    const float* __restrict__ slots, const float* __restrict__ qn,
    const float* __restrict__ clsn, const float* __restrict__ alpha,
    const float* __restrict__ temp, float* __restrict__ out)
{
    __shared__ float sh[4];
    const int i = blockIdx.x, b = blockIdx.y;
    const int w = threadIdx.x>>5, lane = threadIdx.x&31;
    const size_t base = ((size_t)(b*NI + i))*NS;
    const float* qp = qn + (size_t)i*DIM;
    const float* sp = slots + (base+w)*DIM;
    float ss=0.f, dq=0.f;
    #pragma unroll
    for(int q=0;q<8;q++){
        float x=sp[lane+(q<<5)], y=qp[lane+(q<<5)];
        ss+=x*x; dq+=x*y;
    }
    ss=wsum(ss); dq=wsum(dq);
    if(lane==0) sh[w] = dq / fmaxf(sqrtf(ss), 1e-12f);
    __syncthreads();
    float m=fmaxf(fmaxf(sh[0],sh[1]),fmaxf(sh[2],sh[3]));
    float e0=expf(sh[0]-m),e1=expf(sh[1]-m),e2=expf(sh[2]-m),e3=expf(sh[3]-m);
    float inv=1.0f/(e0+e1+e2+e3);
    float a4[4]={e0*inv,e1*inv,e2*inv,e3*inv};
    __syncthreads();
    const int d0=threadIdx.x, d1=threadIdx.x+128;
    float s0=0.f, s1=0.f;
    #pragma unroll
    for(int n=0;n<4;n++){
        const float* rp = slots + (base+n)*DIM;
        s0 += a4[n]*rp[d0]; s1 += a4[n]*rp[d1];
    }
    float pp = wsum(s0*s0 + s1*s1);
    if(lane==0) sh[w]=pp;
    __syncthreads();
    float nrm = fmaxf(sqrtf(sh[0]+sh[1]+sh[2]+sh[3]), 1e-12f);
    float al = *alpha;
    const float* cp = clsn + (size_t)b*DIM;
    float f0 = cp[d0] + al*s0/nrm;
    float f1 = cp[d1] + al*s1/nrm;
    float dot = wsum(f0*qp[d0] + f1*qp[d1]);
    __syncthreads();
    if(lane==0) sh[w]=dot;
    __syncthreads();
    if(threadIdx.x==0)
        out[(size_t)b*NI + i] = (sh[0]+sh[1]+sh[2]+sh[3]) / fmaxf(*temp, 1e-4f);
}

#define GSYM(p, s) cudaGetSymbolAddress((void**)&p, s)

extern "C" void kernel_launch(void* const* d_in, const int* in_sizes, int n_in,
                              void* d_out, int out_size)
{
    const float* tokens=(const float*)d_in[0];
    const float* cls   =(const float*)d_in[1];
    const float* iq    =(const float*)d_in[2];
    const float* noise =(const float*)d_in[3];
    const float* Wk=(const float*)d_in[4],  *bk=(const float*)d_in[5];
    const float* Wv=(const float*)d_in[6],  *bv=(const float*)d_in[7];
    const float* Wqs=(const float*)d_in[8], *bqs=(const float*)d_in[9];
    const float* Wqi=(const float*)d_in[10],*bqi=(const float*)d_in[11];
    const float* ln1g=(const float*)d_in[12],*ln1b=(const float*)d_in[13];
    const float* ln2g=(const float*)d_in[14],*ln2b=(const float*)d_in[15];
    const float* Wf1=(const float*)d_in[16],*bf1=(const float*)d_in[17];
    const float* Wf2=(const float*)d_in[18],*bf2=(const float*)d_in[19];
    const float* mu=(const float*)d_in[20], *sg=(const float*)d_in[21];
    const float* alpha=(const float*)d_in[22],*temp=(const float*)d_in[23];
    float* out=(float*)d_out;

    float *psum,*slots,*qi,*qnp,*clsn,*bkv;
    bf16 *kbf,*vbf,*vt,*qbf,*P,*tokh,*slh,*sll,*hh,*tbh;
    bf16 *WkvTh,*WqsTh,*WqsTl,*Wf1Th,*Wf2Th;
    GSYM(psum,g_psum); GSYM(slots,g_slots);
    GSYM(qi,g_qintent); GSYM(qnp,g_qn); GSYM(clsn,g_clsn); GSYM(bkv,g_bkv);
    GSYM(kbf,g_kbf); GSYM(vbf,g_vbf); GSYM(vt,g_vt); GSYM(qbf,g_qbf); GSYM(P,g_P);
    GSYM(tokh,g_tokh); GSYM(slh,g_slh); GSYM(sll,g_sll);
    GSYM(hh,g_hh); GSYM(tbh,g_tbh);
    GSYM(WkvTh,g_WkvTh);
    GSYM(WqsTh,g_WqsTh); GSYM(WqsTl,g_WqsTl);
    GSYM(Wf1Th,g_Wf1Th); GSYM(Wf2Th,g_Wf2Th);

    cudaFuncSetAttribute(mma_nt<0>, cudaFuncAttributeMaxDynamicSharedMemorySize, 65536);
    cudaFuncSetAttribute(mma_nt<4>, cudaFuncAttributeMaxDynamicSharedMemorySize, 65536);
    cudaFuncSetAttribute(mma_nt<5>, cudaFuncAttributeMaxDynamicSharedMemorySize, 65536);
    cudaFuncSetAttribute(mma_nt<6>, cudaFuncAttributeMaxDynamicSharedMemorySize, 65536);
    cudaFuncSetAttribute(mma_nt<7>, cudaFuncAttributeMaxDynamicSharedMemorySize, 65536);
    cudaFuncSetAttribute(mma_nt<8>, cudaFuncAttributeMaxDynamicSharedMemorySize, 65536);
    cudaFuncSetAttribute(mma_nt3,   cudaFuncAttributeMaxDynamicSharedMemorySize, 131072);

    init_slots_kernel<<<4096,256>>>(noise, mu, sg, slots, slh, sll);
    norm_rows_kernel<<<NI+BSZ,32>>>(iq, cls, qnp, clsn);
    sgemm_nn<<<dim3(2,1),256>>>(iq, Wqi, bqi, qi, NI, DIM, DIM);
    f2bf_kernel<<<(BSZ*SEQ*DIM/4+255)/256,256>>>(tokens, tokh, BSZ*SEQ*DIM/4);
    prep_weights_kernel<<<dim3(17,16,5),256>>>(Wk, Wv, Wqs, Wf1, Wf2, bk, bv,
                                               WkvTh, WqsTh, WqsTl, Wf1Th, Wf2Th, bkv);
    mma_nt<6><<<dim3(4,512,1),256,65536>>>(tokh, WkvTh, kbf, vbf, nullptr, nullptr,
                                           DIM, DIM, 512, DIM, 0,0,0, nullptr, bkv);
    transpose_bf_kernel<<<dim3(SEQ/64, DIM/64, BSZ),256>>>(vbf, vt);

    for(int it=0; it<3; it++){
        mma_nt3<<<dim3(2,4,BSZ),256,131072>>>(slh, sll, WqsTh, WqsTl, bqs, qi,
                                              qbf, psum, DIM, DIM, (size_t)RPB*DIM, (size_t)RPB*DIM);
        mma_nt<0><<<dim3(SEQ/128, RPB/128, BSZ),256,65536>>>(
            qbf, kbf, P, nullptr, psum, nullptr, DIM, DIM, SEQ, DIM,
            (size_t)RPB*DIM, (size_t)SEQ*DIM, (size_t)RPB*SEQ, nullptr, nullptr);
        mma_nt<7><<<dim3(4, RPB/128, BSZ),256,65536>>>(
            P, vt, nullptr, nullptr, psum, slots, SEQ, SEQ, DIM, SEQ/2,
            (size_t)RPB*SEQ, (size_t)DIM*SEQ, (size_t)RPB*DIM, nullptr, nullptr);
        ln_fused_kernel<<<SROWS/8,256>>>(slots, ln1g, ln1b, ln2g, ln2b, hh);
        mma_nt<4><<<dim3(4,128,1),256,65536>>>(hh, Wf1Th, tbh, nullptr, nullptr, nullptr,
                                               DIM, DIM, 2*DIM, DIM, 0,0,0, nullptr, bf1);
        if(it<2)
            mma_nt<5><<<dim3(2,128,1),256,65536>>>(tbh, Wf2Th, slh, sll, nullptr, slots,
                                                   2*DIM, 2*DIM, DIM, 2*DIM, 0,0,0, slots, bf2);
        else
            mma_nt<8><<<dim3(2,128,1),256,65536>>>(tbh, Wf2Th, nullptr, nullptr, nullptr, slots,
                                                   2*DIM, 2*DIM, DIM, 2*DIM, 0,0,0, slots, bf2);
    }
    final_kernel<<<dim3(NI,BSZ),128>>>(slots, qnp, clsn, alpha, temp, out);
}

// round 17
// speedup vs baseline: 1.0276x; 1.0129x over previous
#include <cuda_runtime.h>
#include <cuda_bf16.h>
#include <cstdint>
#include <math.h>

#define NI 128
#define BSZ 32
#define NS 4
#define SEQ 2048
#define DIM 256
#define SROWS (NI*BSZ*NS)
#define RPB (NI*NS)

typedef unsigned long long ull;
typedef __nv_bfloat16 bf16;
typedef __nv_bfloat162 bf162;

__device__ bf16 g_kbf[BSZ*SEQ*DIM];
__device__ bf16 g_vt[BSZ*SEQ*DIM];
__device__ bf16 g_qbf[SROWS*DIM];
__device__ bf16 g_P[(size_t)BSZ*RPB*SEQ];
__device__ float g_psum[SROWS];
__device__ float g_slots[SROWS*DIM];
__device__ float g_qintent[NI*DIM];
__device__ float g_qn[NI*DIM];
__device__ float g_clsn[BSZ*DIM];
__device__ bf16 g_tokh[BSZ*SEQ*DIM];
__device__ bf16 g_slh[SROWS*DIM];
__device__ bf16 g_sll[SROWS*DIM];
__device__ bf16 g_hh[SROWS*DIM];
__device__ bf16 g_tbh[SROWS*2*DIM];
__device__ bf16 g_WkvTh[2*DIM*DIM];
__device__ float g_bkv[2*DIM];
__device__ bf16 g_WqsTh[DIM*DIM];
__device__ bf16 g_WqsTl[DIM*DIM];
__device__ bf16 g_Wf1Th[2*DIM*DIM];
__device__ bf16 g_Wf2Th[2*DIM*DIM];

__device__ __forceinline__ ull fma2(ull a, ull b, ull c){
    ull d; asm("fma.rn.f32x2 %0, %1, %2, %3;" : "=l"(d) : "l"(a),"l"(b),"l"(c)); return d;
}
__device__ __forceinline__ ull pack2(float x, float y){
    ull d; asm("mov.b64 %0, {%1, %2};" : "=l"(d) : "f"(x),"f"(y)); return d;
}
__device__ __forceinline__ float2 up2(ull v){
    float2 r; asm("mov.b64 {%0, %1}, %2;" : "=f"(r.x),"=f"(r.y) : "l"(v)); return r;
}
__device__ __forceinline__ float wsum(float v){
    #pragma unroll
    for(int o=16;o>0;o>>=1) v += __shfl_xor_sync(0xffffffffu, v, o);
    return v;
}
__device__ __forceinline__ uint32_t smem_u32(const void* p){
    uint32_t a; asm("{ .reg .u64 t; cvta.to.shared.u64 t, %1; cvt.u32.u64 %0, t; }" : "=r"(a) : "l"(p));
    return a;
}
#define SW128(o) ((o) ^ (((o)>>3)&0x70))
__device__ __forceinline__ void ldsm4(uint32_t& r0,uint32_t& r1,uint32_t& r2,uint32_t& r3,uint32_t a){
    asm volatile("ldmatrix.sync.aligned.m8n8.x4.shared.b16 {%0,%1,%2,%3}, [%4];"
        : "=r"(r0),"=r"(r1),"=r"(r2),"=r"(r3) : "r"(a) : "memory");
}
__device__ __forceinline__ void mma16816(float* c,uint32_t a0,uint32_t a1,uint32_t a2,uint32_t a3,uint32_t b0,uint32_t b1){
    asm volatile("mma.sync.aligned.m16n8k16.row.col.f32.bf16.bf16.f32 "
        "{%0,%1,%2,%3},{%4,%5,%6,%7},{%8,%9},{%0,%1,%2,%3};"
        : "+f"(c[0]),"+f"(c[1]),"+f"(c[2]),"+f"(c[3])
        : "r"(a0),"r"(a1),"r"(a2),"r"(a3),"r"(b0),"r"(b1));
}
__device__ __forceinline__ void cpa16(uint32_t d, const void* s){
    asm volatile("cp.async.cg.shared.global [%0], [%1], 16;" :: "r"(d), "l"(s));
}
#define CP_COMMIT() asm volatile("cp.async.commit_group;" ::: "memory")
#define CP_WAIT0()  asm volatile("cp.async.wait_group 0;" ::: "memory")
__device__ __forceinline__ float geluf(float x){
    return 0.5f*x*(1.0f+erff(x*0.70710678118654752f));
}

// ============ bf16 NT GEMM, 1-pass, templated mode, pipelined fragments ============
// MODE: 0 softmax (Pb=exp(acc/16), psum atomics); 4 gelu(acc+bias)->Pb;
// 5 acc+bias+res->C fp32 + Pb/Pl split; 6 kv dual-dest (k->Pb rowmajor, v->Pl TRANSPOSED);
// 7 upd split-K atomicAdd; 8 acc+bias+res->C fp32 only
template<int MODE>
__global__ void __launch_bounds__(256,2) mma_nt(
    const bf16* __restrict__ A, const bf16* __restrict__ B,
    bf16* __restrict__ Pb, bf16* __restrict__ Pl,
    float* __restrict__ psum, float* __restrict__ C,
    int lda, int ldb, int ldc, int K,
    size_t sA, size_t sB, size_t sC,
    const float* __restrict__ res, const float* __restrict__ bias)
{
    extern __shared__ char sm[];
    const uint32_t su = smem_u32(sm);
    const int t = threadIdx.x, wid = t>>5, lane = t&31, z = blockIdx.z;
    const int m0 = blockIdx.y<<7;
    int n0, kh = 0;
    if(MODE==7){ n0 = (int)(blockIdx.x&1)<<7; kh = blockIdx.x>>1; }
    else n0 = blockIdx.x<<7;
    A += (size_t)z*sA + (size_t)m0*lda + (size_t)kh*K;
    B += (size_t)z*sB + (size_t)n0*ldb + (size_t)kh*K;
    const int row_ld = t>>3, col_ld = t&7;
    const uint32_t swoff = SW128((uint32_t)(row_ld*128 + col_ld*16));
    const int nsteps = K>>6;
    float acc[2][8][4];
    #pragma unroll
    for(int i=0;i<2;i++)
        #pragma unroll
        for(int j=0;j<8;j++){ acc[i][j][0]=0.f; acc[i][j][1]=0.f; acc[i][j][2]=0.f; acc[i][j][3]=0.f; }
    {
        const bf16* Ag = A + col_ld*8;
        const bf16* Bg = B + col_ld*8;
        #pragma unroll
        for(int j=0;j<4;j++){
            cpa16(su + swoff + j*4096, Ag + (size_t)(row_ld + j*32)*lda);
            cpa16(su + 16384 + swoff + j*4096, Bg + (size_t)(row_ld + j*32)*ldb);
        }
        CP_COMMIT(); CP_WAIT0();
    }
    __syncthreads();
    const int mw = (wid&3)<<5, nw = (wid>>2)<<6;
    const int lrow = lane&15, lkhalf = (lane>>4)*16;
    for(int s=0;s<nsteps;s++){
        const uint32_t bufc = su + (uint32_t)((s&1)*32768);
        if(s+1<nsteps){
            const uint32_t bufn = su + (uint32_t)(((s+1)&1)*32768);
            const bf16* Ag = A + (size_t)(s+1)*64 + col_ld*8;
            const bf16* Bg = B + (size_t)(s+1)*64 + col_ld*8;
            #pragma unroll
            for(int j=0;j<4;j++){
                cpa16(bufn + swoff + j*4096, Ag + (size_t)(row_ld + j*32)*lda);
                cpa16(bufn + 16384 + swoff + j*4096, Bg + (size_t)(row_ld + j*32)*ldb);
            }
            CP_COMMIT();
        }
        uint32_t af[2][2][4];
        uint32_t bfr[2][4];
        {
            #pragma unroll
            for(int mf=0;mf<2;mf++){
                int row = mw + mf*16 + lrow;
                ldsm4(af[0][mf][0],af[0][mf][1],af[0][mf][2],af[0][mf][3],
                      bufc + SW128((uint32_t)(row*128 + lkhalf)));
            }
            int row = nw + lrow;
            ldsm4(bfr[0][0],bfr[0][1],bfr[0][2],bfr[0][3],
                  bufc + 16384 + SW128((uint32_t)(row*128 + lkhalf)));
        }
        #pragma unroll
        for(int i=0;i<16;i++){
            const int kk=i>>2, ng=i&3;
            const int ab = kk&1, bb = i&1;
            if(i<15){
                const int ni=i+1, nkk=ni>>2, nng=ni&3;
                const int nkb = nkk*32 + lkhalf;
                if(nkk!=kk){
                    #pragma unroll
                    for(int mf=0;mf<2;mf++){
                        int row = mw + mf*16 + lrow;
                        ldsm4(af[nkk&1][mf][0],af[nkk&1][mf][1],af[nkk&1][mf][2],af[nkk&1][mf][3],
                              bufc + SW128((uint32_t)(row*128 + nkb)));
                    }
                }
                int row = nw + nng*16 + lrow;
                ldsm4(bfr[bb^1][0],bfr[bb^1][1],bfr[bb^1][2],bfr[bb^1][3],
                      bufc + 16384 + SW128((uint32_t)(row*128 + nkb)));
            }
            #pragma unroll
            for(int mf=0;mf<2;mf++){
                mma16816(acc[mf][ng*2+0], af[ab][mf][0],af[ab][mf][1],af[ab][mf][2],af[ab][mf][3],
                         bfr[bb][0], bfr[bb][2]);
                mma16816(acc[mf][ng*2+1], af[ab][mf][0],af[ab][mf][1],af[ab][mf][2],af[ab][mf][3],
                         bfr[bb][1], bfr[bb][3]);
            }
        }
        if(s+1<nsteps) CP_WAIT0();
        __syncthreads();
    }
    const int gr = lane>>2, gc = (lane&3)<<1;
    if(MODE==0){
        Pb += (size_t)z*sC;
        #pragma unroll
        for(int mf=0;mf<2;mf++){
            const int r0 = m0 + mw + mf*16 + gr, r1 = r0 + 8;
            float s0=0.f, s1=0.f;
            #pragma unroll
            for(int ng=0;ng<4;ng++){
                #pragma unroll
                for(int h=0;h<2;h++){
                    const int col = n0 + nw + ng*16 + h*8 + gc;
                    float* cc = acc[mf][ng*2+h];
                    float e00=__expf(cc[0]*0.0625f), e01=__expf(cc[1]*0.0625f);
                    float e10=__expf(cc[2]*0.0625f), e11=__expf(cc[3]*0.0625f);
                    bf162 p0; p0.x=__float2bfloat16(e00); p0.y=__float2bfloat16(e01);
                    bf162 p1; p1.x=__float2bfloat16(e10); p1.y=__float2bfloat16(e11);
                    *(bf162*)&Pb[(size_t)r0*ldc + col] = p0;
                    *(bf162*)&Pb[(size_t)r1*ldc + col] = p1;
                    s0 += e00+e01; s1 += e10+e11;
                }
            }
            s0 += __shfl_xor_sync(0xffffffffu, s0, 1);
            s0 += __shfl_xor_sync(0xffffffffu, s0, 2);
            s1 += __shfl_xor_sync(0xffffffffu, s1, 1);
            s1 += __shfl_xor_sync(0xffffffffu, s1, 2);
            if((lane&3)==0){
                atomicAdd(&psum[z*RPB + r0], s0);
                atomicAdd(&psum[z*RPB + r1], s1);
            }
        }
    } else if(MODE==7){
        C += (size_t)z*sC;
        #pragma unroll
        for(int mf=0;mf<2;mf++){
            const int r0 = m0 + mw + mf*16 + gr, r1 = r0 + 8;
            const float i0 = 1.0f/psum[z*RPB + r0];
            const float i1 = 1.0f/psum[z*RPB + r1];
            #pragma unroll
            for(int ng=0;ng<4;ng++){
                #pragma unroll
                for(int h=0;h<2;h++){
                    const int col = n0 + nw + ng*16 + h*8 + gc;
                    float* cc = acc[mf][ng*2+h];
                    atomicAdd(&C[(size_t)r0*ldc + col],   cc[0]*i0);
                    atomicAdd(&C[(size_t)r0*ldc + col+1], cc[1]*i0);
                    atomicAdd(&C[(size_t)r1*ldc + col],   cc[2]*i1);
                    atomicAdd(&C[(size_t)r1*ldc + col+1], cc[3]*i1);
                }
            }
        }
    } else if(MODE==6){
        #pragma unroll
        for(int mf=0;mf<2;mf++){
            const int r0 = m0 + mw + mf*16 + gr, r1 = r0 + 8;
            const int bb_ = r0>>11, s0_ = r0&2047, s1_ = r1&2047;
            bf16* vtz = Pl + (size_t)bb_*SEQ*DIM;
            #pragma unroll
            for(int ng=0;ng<4;ng++){
                #pragma unroll
                for(int h=0;h<2;h++){
                    const int col = n0 + nw + ng*16 + h*8 + gc;
                    float* cc = acc[mf][ng*2+h];
                    float b0=bias[col], b1=bias[col+1];
                    bf16 v00=__float2bfloat16(cc[0]+b0), v01=__float2bfloat16(cc[1]+b1);
                    bf16 v10=__float2bfloat16(cc[2]+b0), v11=__float2bfloat16(cc[3]+b1);
                    if(col < 256){
                        bf162 p0; p0.x=v00; p0.y=v01;
                        bf162 p1; p1.x=v10; p1.y=v11;
                        *(bf162*)&Pb[(size_t)r0*256 + col] = p0;
                        *(bf162*)&Pb[(size_t)r1*256 + col] = p1;
                    } else {
                        const int c2 = col - 256;
                        vtz[(size_t)c2*SEQ + s0_]     = v00;
                        vtz[(size_t)(c2+1)*SEQ + s0_] = v01;
                        vtz[(size_t)c2*SEQ + s1_]     = v10;
                        vtz[(size_t)(c2+1)*SEQ + s1_] = v11;
                    }
                }
            }
        }
    } else {
        #pragma unroll
        for(int mf=0;mf<2;mf++){
            const int r0 = m0 + mw + mf*16 + gr, r1 = r0 + 8;
            #pragma unroll
            for(int ng=0;ng<4;ng++){
                #pragma unroll
                for(int h=0;h<2;h++){
                    const int col = n0 + nw + ng*16 + h*8 + gc;
                    float* cc = acc[mf][ng*2+h];
                    float b0=bias[col], b1=bias[col+1];
                    float x00=cc[0]+b0, x01=cc[1]+b1, x10=cc[2]+b0, x11=cc[3]+b1;
                    if(MODE==4){ x00=geluf(x00); x01=geluf(x01); x10=geluf(x10); x11=geluf(x11); }
                    if(MODE==5 || MODE==8){
                        x00 += res[(size_t)r0*ldc + col];
                        x01 += res[(size_t)r0*ldc + col + 1];
                        x10 += res[(size_t)r1*ldc + col];
                        x11 += res[(size_t)r1*ldc + col + 1];
                        C[(size_t)r0*ldc + col]   = x00; C[(size_t)r0*ldc + col+1] = x01;
                        C[(size_t)r1*ldc + col]   = x10; C[(size_t)r1*ldc + col+1] = x11;
                    }
                    if(MODE!=8){
                        bf162 p0; p0.x=__float2bfloat16(x00); p0.y=__float2bfloat16(x01);
                        bf162 p1; p1.x=__float2bfloat16(x10); p1.y=__float2bfloat16(x11);
                        *(bf162*)&Pb[(size_t)r0*ldc + col] = p0;
                        *(bf162*)&Pb[(size_t)r1*ldc + col] = p1;
                        if(MODE==5){
                            bf162 q0, q1;
                            q0.x=__float2bfloat16(x00-__bfloat162float(p0.x));
                            q0.y=__float2bfloat16(x01-__bfloat162float(p0.y));
                            q1.x=__float2bfloat16(x10-__bfloat162float(p1.x));
                            q1.y=__float2bfloat16(x11-__bfloat162float(p1.y));
                            *(bf162*)&Pl[(size_t)r0*ldc + col] = q0;
                            *(bf162*)&Pl[(size_t)r1*ldc + col] = q1;
                        }
                    }
                }
            }
        }
    }
}

// ============ split-bf16 3-pass NT GEMM (qslot), R9 proven version ============
__global__ void __launch_bounds__(256) mma_nt3(
    const bf16* __restrict__ Ah, const bf16* __restrict__ Al,
    const bf16* __restrict__ Bh, const bf16* __restrict__ Bl,
    const float* __restrict__ bias, const float* __restrict__ ext,
    bf16* __restrict__ Cbh, float* __restrict__ psum,
    int ldc, int K, size_t sA, size_t sC)
{
    extern __shared__ char sm[];
    const uint32_t su = smem_u32(sm);
    const int t = threadIdx.x, wid = t>>5, lane = t&31, z = blockIdx.z;
    const int m0 = blockIdx.y<<7, n0 = blockIdx.x<<7;
    if(blockIdx.x==0 && t<128) psum[z*RPB + m0 + t] = 0.f;
    Ah += (size_t)z*sA + (size_t)m0*K;
    Al += (size_t)z*sA + (size_t)m0*K;
    Bh += (size_t)n0*K;
    Bl += (size_t)n0*K;
    const int row_ld = t>>3, col_ld = t&7;
    const uint32_t swoff = SW128((uint32_t)(row_ld*128 + col_ld*16));
    const int nsteps = K>>6;
    float acc[2][8][4];
    #pragma unroll
    for(int i=0;i<2;i++)
        #pragma unroll
        for(int j=0;j<8;j++){ acc[i][j][0]=0.f; acc[i][j][1]=0.f; acc[i][j][2]=0.f; acc[i][j][3]=0.f; }
    {
        #pragma unroll
        for(int j=0;j<4;j++){
            size_t ro = (size_t)(row_ld + j*32)*K + col_ld*8;
            cpa16(su +         swoff + j*4096, Ah + ro);
            cpa16(su + 16384 + swoff + j*4096, Al + ro);
            cpa16(su + 32768 + swoff + j*4096, Bh + ro);
            cpa16(su + 49152 + swoff + j*4096, Bl + ro);
        }
        CP_COMMIT(); CP_WAIT0();
    }
    __syncthreads();
    const int mw = (wid&3)<<5, nw = (wid>>2)<<6;
    for(int s=0;s<nsteps;s++){
        const uint32_t bufc = su + (uint32_t)((s&1)*65536);
        if(s+1<nsteps){
            const uint32_t bufn = su + (uint32_t)(((s+1)&1)*65536);
            const size_t ko = (size_t)(s+1)*64 + col_ld*8;
            #pragma unroll
            for(int j=0;j<4;j++){
                size_t ro = (size_t)(row_ld + j*32)*K + ko;
                cpa16(bufn +         swoff + j*4096, Ah + ro);
                cpa16(bufn + 16384 + swoff + j*4096, Al + ro);
                cpa16(bufn + 32768 + swoff + j*4096, Bh + ro);
                cpa16(bufn + 49152 + swoff + j*4096, Bl + ro);
            }
            CP_COMMIT();
        }
        #pragma unroll
        for(int kk=0;kk<4;kk++){
            const int kb = kk*32 + ((lane>>4)*16);
            uint32_t ah[2][4], al[2][4];
            #pragma unroll
            for(int mf=0;mf<2;mf++){
                int row = mw + mf*16 + (lane&15);
                uint32_t so = SW128((uint32_t)(row*128 + kb));
                ldsm4(ah[mf][0],ah[mf][1],ah[mf][2],ah[mf][3], bufc + so);
                ldsm4(al[mf][0],al[mf][1],al[mf][2],al[mf][3], bufc + 16384 + so);
            }
            #pragma unroll
            for(int ng=0;ng<4;ng++){
                int row = nw + ng*16 + (lane&15);
                uint32_t so = SW128((uint32_t)(row*128 + kb));
                uint32_t bh0,bh1,bh2,bh3, bl0,bl1,bl2,bl3;
                ldsm4(bh0,bh1,bh2,bh3, bufc + 32768 + so);
                ldsm4(bl0,bl1,bl2,bl3, bufc + 49152 + so);
                #pragma unroll
                for(int mf=0;mf<2;mf++){
                    mma16816(acc[mf][ng*2+0], ah[mf][0],ah[mf][1],ah[mf][2],ah[mf][3], bh0, bh2);
                    mma16816(acc[mf][ng*2+1], ah[mf][0],ah[mf][1],ah[mf][2],ah[mf][3], bh1, bh3);
                    mma16816(acc[mf][ng*2+0], ah[mf][0],ah[mf][1],ah[mf][2],ah[mf][3], bl0, bl2);
                    mma16816(acc[mf][ng*2+1], ah[mf][0],ah[mf][1],ah[mf][2],ah[mf][3], bl1, bl3);
                    mma16816(acc[mf][ng*2+0], al[mf][0],al[mf][1],al[mf][2],al[mf][3], bh0, bh2);
                    mma16816(acc[mf][ng*2+1], al[mf][0],al[mf][1],al[mf][2],al[mf][3], bh1, bh3);
                }
            }
        }
        if(s+1<nsteps) CP_WAIT0();
        __syncthreads();
    }
    Cbh += (size_t)z*sC;
    const int gr = lane>>2, gc = (lane&3)<<1;
    #pragma unroll
    for(int mf=0;mf<2;mf++){
        const int r0 = m0 + mw + mf*16 + gr, r1 = r0 + 8;
        #pragma unroll
        for(int ng=0;ng<4;ng++){
            #pragma unroll
            for(int h=0;h<2;h++){
                const int col = n0 + nw + ng*16 + h*8 + gc;
                float* cc = acc[mf][ng*2+h];
                float b0=bias[col], b1=bias[col+1];
                float x00=cc[0]+b0+ext[(size_t)(r0>>2)*ldc + col];
                float x01=cc[1]+b1+ext[(size_t)(r0>>2)*ldc + col + 1];
                float x10=cc[2]+b0+ext[(size_t)(r1>>2)*ldc + col];
                float x11=cc[3]+b1+ext[(size_t)(r1>>2)*ldc + col + 1];
                bf162 p0; p0.x=__float2bfloat16(x00); p0.y=__float2bfloat16(x01);
                bf162 p1; p1.x=__float2bfloat16(x10); p1.y=__float2bfloat16(x11);
                *(bf162*)&Cbh[(size_t)r0*ldc + col] = p0;
                *(bf162*)&Cbh[(size_t)r1*ldc + col] = p1;
            }
        }
    }
}

__global__ void __launch_bounds__(256) f2bf_kernel(
    const float* __restrict__ x, bf16* __restrict__ y, int n4)
{
    int i = blockIdx.x*blockDim.x + threadIdx.x;
    if (i >= n4) return;
    float4 v = ((const float4*)x)[i];
    bf162 a; a.x=__float2bfloat16(v.x); a.y=__float2bfloat16(v.y);
    bf162 b; b.x=__float2bfloat16(v.z); b.y=__float2bfloat16(v.w);
    ((bf162*)y)[2*i] = a;
    ((bf162*)y)[2*i+1] = b;
}

__global__ void __launch_bounds__(256) prep_weights_kernel(
    const float* __restrict__ Wk, const float* __restrict__ Wv,
    const float* __restrict__ Wqs, const float* __restrict__ Wf1,
    const float* __restrict__ Wf2, const float* __restrict__ bk,
    const float* __restrict__ bv,
    bf16* __restrict__ WkvTh, bf16* __restrict__ WqsTh, bf16* __restrict__ WqsTl,
    bf16* __restrict__ Wf1Th, bf16* __restrict__ Wf2Th, float* __restrict__ bkv)
{
    __shared__ float tl[32][33];
    const int zz = blockIdx.z, t = threadIdx.x, r = t>>5, c = t&31;
    if(zz==0 && blockIdx.x==8 && blockIdx.y==0){
        bkv[t] = bk[t]; bkv[256+t] = bv[t];
        return;
    }
    const float* W; bf16 *Th, *Tl=nullptr; int K, N, noff=0;
    if(zz==0){ W=Wk; Th=WkvTh; K=DIM; N=DIM; }
    else if(zz==1){ W=Wv; Th=WkvTh; K=DIM; N=DIM; noff=256; }
    else if(zz==2){ W=Wqs; Th=WqsTh; Tl=WqsTl; K=DIM; N=DIM; }
    else if(zz==3){ W=Wf1; Th=Wf1Th; K=DIM; N=2*DIM; }
    else { W=Wf2; Th=Wf2Th; K=2*DIM; N=DIM; }
    const int k0 = blockIdx.x<<5, n0 = blockIdx.y<<5;
    if(k0 >= K || n0 >= N) return;
    #pragma unroll
    for(int j=0;j<4;j++)
        tl[r+j*8][c] = W[(size_t)(k0+r+j*8)*N + n0 + c];
    __syncthreads();
    #pragma unroll
    for(int j=0;j<4;j++){
        float x = tl[c][r+j*8];
        bf16 h = __float2bfloat16(x);
        Th[(size_t)(noff+n0+r+j*8)*K + k0 + c] = h;
        if(Tl) Tl[(size_t)(n0+r+j*8)*K + k0 + c] = __float2bfloat16(x-__bfloat162float(h));
    }
}

__global__ void __launch_bounds__(256) sgemm_nn(
    const float* __restrict__ A, const float* __restrict__ B,
    const float* __restrict__ bias, float* __restrict__ C,
    int M, int N, int K)
{
    __shared__ float As[8][132];
    __shared__ float Bs[8][128];
    const int t = threadIdx.x;
    const int m0 = blockIdx.y<<7, n0 = blockIdx.x<<7;
    const int arow = t>>1, acol = (t&1)<<2;
    const int brow = t>>5, bcol = (t&31)<<2;
    const float* Ap = A + (size_t)(m0+arow)*K + acol;
    const float* Bp = B + (size_t)brow*N + n0 + bcol;
    float4 ar = *(const float4*)Ap;
    float4 br = *(const float4*)Bp;
    ull c2[8][4];
    #pragma unroll
    for(int i=0;i<8;i++){ c2[i][0]=0; c2[i][1]=0; c2[i][2]=0; c2[i][3]=0; }
    const int tm=(t>>4)<<3, tn=(t&15)<<3;
    const int nt = K>>3;
    for(int kt=0;kt<nt;kt++){
        As[acol+0][arow]=ar.x; As[acol+1][arow]=ar.y;
        As[acol+2][arow]=ar.z; As[acol+3][arow]=ar.w;
        *(float4*)&Bs[brow][bcol]=br;
        __syncthreads();
        if(kt+1<nt){
            ar = *(const float4*)(Ap + ((kt+1)<<3));
            br = *(const float4*)(Bp + (size_t)((kt+1)<<3)*N);
        }
        #pragma unroll
        for(int kk=0;kk<8;kk++){
            float4 a0=*(const float4*)&As[kk][tm];
            float4 a1=*(const float4*)&As[kk][tm+4];
            ulonglong2 w0=*(const ulonglong2*)&Bs[kk][tn];
            ulonglong2 w1=*(const ulonglong2*)&Bs[kk][tn+4];
            float a[8]={a0.x,a0.y,a0.z,a0.w,a1.x,a1.y,a1.z,a1.w};
            #pragma unroll
            for(int i=0;i<8;i++){
                ull ap = pack2(a[i],a[i]);
                c2[i][0]=fma2(ap,w0.x,c2[i][0]);
                c2[i][1]=fma2(ap,w0.y,c2[i][1]);
                c2[i][2]=fma2(ap,w1.x,c2[i][2]);
                c2[i][3]=fma2(ap,w1.y,c2[i][3]);
            }
        }
        __syncthreads();
    }
    #pragma unroll
    for(int i=0;i<8;i++){
        const int row=m0+tm+i;
        float v[8];
        #pragma unroll
        for(int p=0;p<4;p++){ float2 u=up2(c2[i][p]); v[2*p]=u.x; v[2*p+1]=u.y; }
        #pragma unroll
        for(int j=0;j<8;j++) v[j] += bias[n0+tn+j];
        *(float4*)&C[(size_t)row*N + n0+tn]   = make_float4(v[0],v[1],v[2],v[3]);
        *(float4*)&C[(size_t)row*N + n0+tn+4] = make_float4(v[4],v[5],v[6],v[7]);
    }
}

__global__ void init_slots_kernel(const float* __restrict__ noise,
                                  const float* __restrict__ mu,
                                  const float* __restrict__ sigma,
                                  float* __restrict__ slots,
                                  bf16* __restrict__ slh, bf16* __restrict__ sll)
{
    for(int idx = blockIdx.x*blockDim.x + threadIdx.x; idx < SROWS*DIM;
        idx += gridDim.x*blockDim.x){
        int d = idx & 255, ns = (idx>>8)&3, i = (idx>>10)&127, b = idx>>17;
        float val = mu[ns*DIM+d] + noise[(size_t)(((i*BSZ+b)*NS+ns))*DIM+d]*sigma[ns*DIM+d];
        slots[idx] = val;
        bf16 hv = __float2bfloat16(val);
        slh[idx] = hv;
        sll[idx] = __float2bfloat16(val - __bfloat162float(hv));
    }
}

__global__ void norm_rows_kernel(const float* __restrict__ iq,
                                 const float* __restrict__ cls,
                                 float* __restrict__ qn, float* __restrict__ clsn)
{
    const int row = blockIdx.x, lane = threadIdx.x;
    const float* src; float* dst;
    if(row < NI){ src = iq + (size_t)row*DIM; dst = qn + (size_t)row*DIM; }
    else        { src = cls + (size_t)(row-NI)*DIM; dst = clsn + (size_t)(row-NI)*DIM; }
    float4 a0=*(const float4*)(src + (lane<<2));
    float4 a1=*(const float4*)(src + 128 + (lane<<2));
    float ss=a0.x*a0.x+a0.y*a0.y+a0.z*a0.z+a0.w*a0.w
            +a1.x*a1.x+a1.y*a1.y+a1.z*a1.z+a1.w*a1.w;
    ss = wsum(ss);
    float inv = 1.0f/fmaxf(sqrtf(ss), 1e-12f);
    *(float4*)(dst+(lane<<2))     = make_float4(a0.x*inv,a0.y*inv,a0.z*inv,a0.w*inv);
    *(float4*)(dst+128+(lane<<2)) = make_float4(a1.x*inv,a1.y*inv,a1.z*inv,a1.w*inv);
}

__global__ void __launch_bounds__(256) ln_fused_kernel(
    float* __restrict__ slots,
    const float* __restrict__ g1, const float* __restrict__ b1,
    const float* __restrict__ g2, const float* __restrict__ b2,
    bf16* __restrict__ hh)
{
    const int row = (blockIdx.x<<3) + (threadIdx.x>>5);
    const int lane = threadIdx.x & 31;
    float* xp = slots + (size_t)row*DIM;
    float4 a0=*(const float4*)(xp+(lane<<2));
    float4 a1=*(const float4*)(xp+128+(lane<<2));
    float v[8]={a0.x,a0.y,a0.z,a0.w,a1.x,a1.y,a1.z,a1.w};
    float s1=0.f,s2=0.f;
    #pragma unroll
    for(int q=0;q<8;q++){ s1+=v[q]; s2+=v[q]*v[q]; }
    s1=wsum(s1); s2=wsum(s2);
    float mean=s1*(1.0f/256.0f);
    float rstd=rsqrtf(s2*(1.0f/256.0f)-mean*mean + 1e-5f);
    float4 g10=*(const float4*)(g1+(lane<<2)),  g11=*(const float4*)(g1+128+(lane<<2));
    float4 b10=*(const float4*)(b1+(lane<<2)),  b11=*(const float4*)(b1+128+(lane<<2));
    float o[8];
    o[0]=(v[0]-mean)*rstd*g10.x+b10.x; o[1]=(v[1]-mean)*rstd*g10.y+b10.y;
    o[2]=(v[2]-mean)*rstd*g10.z+b10.z; o[3]=(v[3]-mean)*rstd*g10.w+b10.w;
    o[4]=(v[4]-mean)*rstd*g11.x+b11.x; o[5]=(v[5]-mean)*rstd*g11.y+b11.y;
    o[6]=(v[6]-mean)*rstd*g11.z+b11.z; o[7]=(v[7]-mean)*rstd*g11.w+b11.w;
    *(float4*)(xp+(lane<<2))     = make_float4(o[0],o[1],o[2],o[3]);
    *(float4*)(xp+128+(lane<<2)) = make_float4(o[4],o[5],o[6],o[7]);
    float t1=0.f,t2=0.f;
    #pragma unroll
    for(int q=0;q<8;q++){ t1+=o[q]; t2+=o[q]*o[q]; }
    t1=wsum(t1); t2=wsum(t2);
    float mean2=t1*(1.0f/256.0f);
    float rstd2=rsqrtf(t2*(1.0f/256.0f)-mean2*mean2 + 1e-5f);
    float4 g20=*(const float4*)(g2+(lane<<2)),  g21=*(const float4*)(g2+128+(lane<<2));
    float4 b20=*(const float4*)(b2+(lane<<2)),  b21=*(const float4*)(b2+128+(lane<<2));
    bf16 hb[8];
    hb[0]=__float2bfloat16((o[0]-mean2)*rstd2*g20.x+b20.x);
    hb[1]=__float2bfloat16((o[1]-mean2)*rstd2*g20.y+b20.y);
    hb[2]=__float2bfloat16((o[2]-mean2)*rstd2*g20.z+b20.z);
    hb[3]=__float2bfloat16((o[3]-mean2)*rstd2*g20.w+b20.w);
    hb[4]=__float2bfloat16((o[4]-mean2)*rstd2*g21.x+b21.x);
    hb[5]=__float2bfloat16((o[5]-mean2)*rstd2*g21.y+b21.y);
    hb[6]=__float2bfloat16((o[6]-mean2)*rstd2*g21.z+b21.z);
    hb[7]=__float2bfloat16((o[7]-mean2)*rstd2*g21.w+b21.w);
    *(uint2*)(hh + (size_t)row*DIM + (lane<<2))       = *(uint2*)hb;
    *(uint2*)(hh + (size_t)row*DIM + 128 + (lane<<2)) = *(uint2*)(hb+4);
}

__global__ void __launch_bounds__(128) final_kernel(
    const float* __restrict__ slots, const float* __restrict__ qn,
    const float* __restrict__ clsn, const float* __restrict__ alpha,
    const float* __restrict__ temp, float* __restrict__ out)
{
    __shared__ float sh[4];
    const int i = blockIdx.x, b = blockIdx.y;
    const int w = threadIdx.x>>5, lane = threadIdx.x&31;
    const size_t base = ((size_t)(b*NI + i))*NS;
    const float* qp = qn + (size_t)i*DIM;
    const float* sp = slots + (base+w)*DIM;
    float ss=0.f, dq=0.f;
    #pragma unroll
    for(int q=0;q<8;q++){
        float x=sp[lane+(q<<5)], y=qp[lane+(q<<5)];
        ss+=x*x; dq+=x*y;
    }
    ss=wsum(ss); dq=wsum(dq);
    if(lane==0) sh[w] = dq / fmaxf(sqrtf(ss), 1e-12f);
    __syncthreads();
    float m=fmaxf(fmaxf(sh[0],sh[1]),fmaxf(sh[2],sh[3]));
    float e0=expf(sh[0]-m),e1=expf(sh[1]-m),e2=expf(sh[2]-m),e3=expf(sh[3]-m);
    float inv=1.0f/(e0+e1+e2+e3);
    float a4[4]={e0*inv,e1*inv,e2*inv,e3*inv};
    __syncthreads();
    const int d0=threadIdx.x, d1=threadIdx.x+128;
    float s0=0.f, s1=0.f;
    #pragma unroll
    for(int n=0;n<4;n++){
        const float* rp = slots + (base+n)*DIM;
        s0 += a4[n]*rp[d0]; s1 += a4[n]*rp[d1];
    }
    float pp = wsum(s0*s0 + s1*s1);
    if(lane==0) sh[w]=pp;
    __syncthreads();
    float nrm = fmaxf(sqrtf(sh[0]+sh[1]+sh[2]+sh[3]), 1e-12f);
    float al = *alpha;
    const float* cp = clsn + (size_t)b*DIM;
    float f0 = cp[d0] + al*s0/nrm;
    float f1 = cp[d1] + al*s1/nrm;
    float dot = wsum(f0*qp[d0] + f1*qp[d1]);
    __syncthreads();
    if(lane==0) sh[w]=dot;
    __syncthreads();
    if(threadIdx.x==0)
        out[(size_t)b*NI + i] = (sh[0]+sh[1]+sh[2]+sh[3]) / fmaxf(*temp, 1e-4f);
}

#define GSYM(p, s) cudaGetSymbolAddress((void**)&p, s)

extern "C" void kernel_launch(void* const* d_in, const int* in_sizes, int n_in,
                              void* d_out, int out_size)
{
    const float* tokens=(const float*)d_in[0];
    const float* cls   =(const float*)d_in[1];
    const float* iq    =(const float*)d_in[2];
    const float* noise =(const float*)d_in[3];
    const float* Wk=(const float*)d_in[4],  *bk=(const float*)d_in[5];
    const float* Wv=(const float*)d_in[6],  *bv=(const float*)d_in[7];
    const float* Wqs=(const float*)d_in[8], *bqs=(const float*)d_in[9];
    const float* Wqi=(const float*)d_in[10],*bqi=(const float*)d_in[11];
    const float* ln1g=(const float*)d_in[12],*ln1b=(const float*)d_in[13];
    const float* ln2g=(const float*)d_in[14],*ln2b=(const float*)d_in[15];
    const float* Wf1=(const float*)d_in[16],*bf1=(const float*)d_in[17];
    const float* Wf2=(const float*)d_in[18],*bf2=(const float*)d_in[19];
    const float* mu=(const float*)d_in[20], *sg=(const float*)d_in[21];
    const float* alpha=(const float*)d_in[22],*temp=(const float*)d_in[23];
    float* out=(float*)d_out;

    float *psum,*slots,*qi,*qnp,*clsn,*bkv;
    bf16 *kbf,*vt,*qbf,*P,*tokh,*slh,*sll,*hh,*tbh;
    bf16 *WkvTh,*WqsTh,*WqsTl,*Wf1Th,*Wf2Th;
    GSYM(psum,g_psum); GSYM(slots,g_slots);
    GSYM(qi,g_qintent); GSYM(qnp,g_qn); GSYM(clsn,g_clsn); GSYM(bkv,g_bkv);
    GSYM(kbf,g_kbf); GSYM(vt,g_vt); GSYM(qbf,g_qbf); GSYM(P,g_P);
    GSYM(tokh,g_tokh); GSYM(slh,g_slh); GSYM(sll,g_sll);
    GSYM(hh,g_hh); GSYM(tbh,g_tbh);
    GSYM(WkvTh,g_WkvTh);
    GSYM(WqsTh,g_WqsTh); GSYM(WqsTl,g_WqsTl);
    GSYM(Wf1Th,g_Wf1Th); GSYM(Wf2Th,g_Wf2Th);

    cudaFuncSetAttribute(mma_nt<0>, cudaFuncAttributeMaxDynamicSharedMemorySize, 65536);
    cudaFuncSetAttribute(mma_nt<4>, cudaFuncAttributeMaxDynamicSharedMemorySize, 65536);
    cudaFuncSetAttribute(mma_nt<5>, cudaFuncAttributeMaxDynamicSharedMemorySize, 65536);
    cudaFuncSetAttribute(mma_nt<6>, cudaFuncAttributeMaxDynamicSharedMemorySize, 65536);
    cudaFuncSetAttribute(mma_nt<7>, cudaFuncAttributeMaxDynamicSharedMemorySize, 65536);
    cudaFuncSetAttribute(mma_nt<8>, cudaFuncAttributeMaxDynamicSharedMemorySize, 65536);
    cudaFuncSetAttribute(mma_nt3,   cudaFuncAttributeMaxDynamicSharedMemorySize, 131072);

    init_slots_kernel<<<4096,256>>>(noise, mu, sg, slots, slh, sll);
    norm_rows_kernel<<<NI+BSZ,32>>>(iq, cls, qnp, clsn);
    sgemm_nn<<<dim3(2,1),256>>>(iq, Wqi, bqi, qi, NI, DIM, DIM);
    f2bf_kernel<<<(BSZ*SEQ*DIM/4+255)/256,256>>>(tokens, tokh, BSZ*SEQ*DIM/4);
    prep_weights_kernel<<<dim3(17,16,5),256>>>(Wk, Wv, Wqs, Wf1, Wf2, bk, bv,
                                               WkvTh, WqsTh, WqsTl, Wf1Th, Wf2Th, bkv);
    // kv projection: k -> kbf row-major, v -> vt TRANSPOSED directly from epilogue
    mma_nt<6><<<dim3(4,512,1),256,65536>>>(tokh, WkvTh, kbf, vt, nullptr, nullptr,
                                           DIM, DIM, 512, DIM, 0,0,0, nullptr, bkv);

    for(int it=0; it<3; it++){
        mma_nt3<<<dim3(2,4,BSZ),256,131072>>>(slh, sll, WqsTh, WqsTl, bqs, qi,
                                              qbf, psum, DIM, DIM, (size_t)RPB*DIM, (size_t)RPB*DIM);
        mma_nt<0><<<dim3(SEQ/128, RPB/128, BSZ),256,65536>>>(
            qbf, kbf, P, nullptr, psum, nullptr, DIM, DIM, SEQ, DIM,
            (size_t)RPB*DIM, (size_t)SEQ*DIM, (size_t)RPB*SEQ, nullptr, nullptr);
        mma_nt<7><<<dim3(4, RPB/128, BSZ),256,65536>>>(
            P, vt, nullptr, nullptr, psum, slots, SEQ, SEQ, DIM, SEQ/2,
            (size_t)RPB*SEQ, (size_t)DIM*SEQ, (size_t)RPB*DIM, nullptr, nullptr);
        ln_fused_kernel<<<SROWS/8,256>>>(slots, ln1g, ln1b, ln2g, ln2b, hh);
        mma_nt<4><<<dim3(4,128,1),256,65536>>>(hh, Wf1Th, tbh, nullptr, nullptr, nullptr,
                                               DIM, DIM, 2*DIM, DIM, 0,0,0, nullptr, bf1);
        if(it<2)
            mma_nt<5><<<dim3(2,128,1),256,65536>>>(tbh, Wf2Th, slh, sll, nullptr, slots,
                                                   2*DIM, 2*DIM, DIM, 2*DIM, 0,0,0, slots, bf2);
        else
            mma_nt<8><<<dim3(2,128,1),256,65536>>>(tbh, Wf2Th, nullptr, nullptr, nullptr, slots,
                                                   2*DIM, 2*DIM, DIM, 2*DIM, 0,0,0, slots, bf2);
    }
    final_kernel<<<dim3(NI,BSZ),128>>>(slots, qnp, clsn, alpha, temp, out);
}